// round 11
// baseline (speedup 1.0000x reference)
#include <cuda_runtime.h>
#include <math.h>

#define NCH    131072
#define NSTEPS 60
#define HDIM   128
#define THREADS 384
#define PAIRS   6

typedef unsigned long long ull;

// ---------------------------------------------------------------------------
// Packed fp32x2 helpers (sm_103a FFMA2 — only reachable via PTX f32x2 ops).
// ---------------------------------------------------------------------------
static __device__ __forceinline__ ull pack2(float lo, float hi) {
    ull r; asm("mov.b64 %0, {%1, %2};" : "=l"(r) : "f"(lo), "f"(hi)); return r;
}
static __device__ __forceinline__ void unpack2(ull v, float& lo, float& hi) {
    asm("mov.b64 {%0, %1}, %2;" : "=f"(lo), "=f"(hi) : "l"(v));
}
static __device__ __forceinline__ void fma2(ull& c, ull a, ull b) {
    asm("fma.rn.f32x2 %0, %1, %2, %0;" : "+l"(c) : "l"(a), "l"(b));
}

static __device__ __forceinline__ void silu_act(float a, float& h, float& sp) {
    float e   = __expf(-a);
    float sig = __fdividef(1.0f, 1.0f + e);
    h  = a * sig;
    sp = sig * (1.0f + a * (1.0f - sig));
}
static __device__ __forceinline__ float silu_prime(float a) {
    float e   = __expf(-a);
    float sig = __fdividef(1.0f, 1.0f + e);
    return sig * (1.0f + a * (1.0f - sig));
}

#define PBAR(id) asm volatile("bar.sync %0, 64;" :: "r"(id) : "memory")

// ---------------------------------------------------------------------------
// 12 warps = 6 warp-pairs; each pair owns 8 chains and one 4 KB buffer.
// Warp half w of a pair owns outputs/rows j0 = 64w + 4(t&7) + (t>>3),
// j1 = j0 + 32.  (j>>2)&7 == t&7 for both, so every swizzled access below is
// conflict-free per quarter-warp phase.
//
// Activations (pair-major, swizzled 16B slots): slot(k,half) = (2k+half) ^
// ((k>>2)&7); half0 = f32x2 pairs (s0,s1),(s2,s3), half1 = (s4..s7).
// Backward d-buffer: plain sample-major d[s][j] at s*512 + 4j bytes.
// Weights: quad q of row k at slot q ^ ((k>>2)&7)  (row stride 512 B).
// ---------------------------------------------------------------------------

// Forward 128->128: warp half computes its 64 outputs (2 per lane) for 8
// samples, sample-pair packed FMA2. SEED: layer 4 writes d_a4 directly.
template<bool SEED>
static __device__ __forceinline__ void fwd_pair(
    const char* __restrict__ Ws, char* __restrict__ ab,
    float ba, float bb, float* __restrict__ sp,
    float w5a, float w5b, float* __restrict__ dbuf,
    int q0s, int q08s, int bsel4, int j0, int j1, int barid,
    const int* __restrict__ stofs)
{
    ull acc[4][2];
    {
        ull bd0 = pack2(ba, ba), bd1 = pack2(bb, bb);
#pragma unroll
        for (int p = 0; p < 4; p++) { acc[p][0] = bd0; acc[p][1] = bd1; }
    }
    const char* WsB = Ws + bsel4;
#pragma unroll 1
    for (int k0 = 0; k0 < HDIM; k0 += 32) {     // swizzle period
        const char* wb = WsB + k0 * 512;
        const char* hb = ab  + k0 * 32;
#pragma unroll
        for (int kk = 0; kk < 32; kk++) {
            const int c  = (kk >> 2) & 7;        // compile-time
            const int cs = c << 4;
            float wv0 = *(const float*)(wb + kk * 512 + (q0s  ^ cs));
            float wv1 = *(const float*)(wb + kk * 512 + (q08s ^ cs));
            ull wd0 = pack2(wv0, wv0), wd1 = pack2(wv1, wv1);
            ulonglong2 hA = *(const ulonglong2*)(hb + (((2*kk    ) ^ c) << 4));
            ulonglong2 hB = *(const ulonglong2*)(hb + (((2*kk + 1) ^ c) << 4));
            fma2(acc[0][0], hA.x, wd0); fma2(acc[0][1], hA.x, wd1);
            fma2(acc[1][0], hA.y, wd0); fma2(acc[1][1], hA.y, wd1);
            fma2(acc[2][0], hB.x, wd0); fma2(acc[2][1], hB.x, wd1);
            fma2(acc[3][0], hB.y, wd0); fma2(acc[3][1], hB.y, wd1);
        }
    }
    PBAR(barid);    // both halves done reading ab before it is overwritten

    if (!SEED) {
        ull hh[4][2];
#pragma unroll
        for (int p = 0; p < 4; p++)
#pragma unroll
            for (int jl = 0; jl < 2; jl++) {
                float a0, a1; unpack2(acc[p][jl], a0, a1);
                float h0, s0, h1, s1;
                silu_act(a0, h0, s0);
                silu_act(a1, h1, s1);
                sp[jl * 8 + 2 * p]     = s0;
                sp[jl * 8 + 2 * p + 1] = s1;
                hh[p][jl] = pack2(h0, h1);
            }
        *(ulonglong2*)(ab + stofs[0]) = make_ulonglong2(hh[0][0], hh[1][0]);
        *(ulonglong2*)(ab + stofs[1]) = make_ulonglong2(hh[2][0], hh[3][0]);
        *(ulonglong2*)(ab + stofs[2]) = make_ulonglong2(hh[0][1], hh[1][1]);
        *(ulonglong2*)(ab + stofs[3]) = make_ulonglong2(hh[2][1], hh[3][1]);
        PBAR(barid);
    } else {
        // d_a4 = w5 (.) silu'(a4) -> sample-major dbuf (rows j0, j1 only)
#pragma unroll
        for (int p = 0; p < 4; p++) {
            float a0, a1, c0, c1;
            unpack2(acc[p][0], a0, a1);
            unpack2(acc[p][1], c0, c1);
            dbuf[(2*p    ) * HDIM + j0] = w5a * silu_prime(a0);
            dbuf[(2*p    ) * HDIM + j1] = w5b * silu_prime(c0);
            dbuf[(2*p + 1) * HDIM + j0] = w5a * silu_prime(a1);
            dbuf[(2*p + 1) * HDIM + j1] = w5b * silu_prime(c1);
        }
        PBAR(barid);
    }
}

// Backward through W^T: warp half computes rows j0, j1 (2 per lane), summing
// over ALL 128 j (j-packed f32x2, hsum at the end). No cross-warp reduction.
static __device__ __forceinline__ void bwd_pair(
    const char* __restrict__ Ws, const char* __restrict__ db,
    int j0, int j1, int a, int barid, float accf[8][2])
{
    ull acc[8][2];
    const ull z = pack2(0.0f, 0.0f);
#pragma unroll
    for (int s = 0; s < 8; s++) { acc[s][0] = z; acc[s][1] = z; }

    const char* wrA = Ws + j0 * 512;
    const char* wrB = Ws + j1 * 512;

#pragma unroll 1
    for (int qi = 0; qi < 8; qi++) {            // quad = 8g + qi
        const int wo   = (qi ^ a) << 4;
        const int dofs = qi << 4;
#pragma unroll
        for (int g = 0; g < 4; g++) {
            const int go = g * 128;
            ulonglong2 wA = *(const ulonglong2*)(wrA + go + wo);
            ulonglong2 wB = *(const ulonglong2*)(wrB + go + wo);
#pragma unroll
            for (int s = 0; s < 8; s++) {
                ulonglong2 dv = *(const ulonglong2*)(db + s * 512 + go + dofs);
                fma2(acc[s][0], dv.x, wA.x); fma2(acc[s][0], dv.y, wA.y);
                fma2(acc[s][1], dv.x, wB.x); fma2(acc[s][1], dv.y, wB.y);
            }
        }
    }
    PBAR(barid);    // both halves done reading db before it is overwritten

#pragma unroll
    for (int s = 0; s < 8; s++) {
        float lo, hi;
        unpack2(acc[s][0], lo, hi); accf[s][0] = lo + hi;
        unpack2(acc[s][1], lo, hi); accf[s][1] = lo + hi;
    }
}

// smem: 3 x 64KB swizzled weights + 6 pairs x 4KB buffers + 1KB w1 = 222208 B
extern "C" __global__ void __launch_bounds__(THREADS, 1)
ebm_langevin_kernel(const float* __restrict__ x0,
                    const float* __restrict__ w1, const float* __restrict__ b1,
                    const float* __restrict__ w2, const float* __restrict__ b2,
                    const float* __restrict__ w3, const float* __restrict__ b3,
                    const float* __restrict__ w4, const float* __restrict__ b4,
                    const float* __restrict__ w5, const float* __restrict__ b5,
                    const float* __restrict__ noise,
                    float* __restrict__ out)
{
    extern __shared__ float smem[];
    float* w2s  = smem;
    float* w3s  = smem + 16384;
    float* w4s  = smem + 32768;
    char*  bufs = (char*)(smem + 49152);
    float* w1sm = (float*)(bufs + PAIRS * 4096);   // 256 floats

    const int tid = threadIdx.x;

    // Cooperative swizzled weight load: quad q of row k -> slot q ^ ((k>>2)&7).
    for (int idx = tid; idx < 3 * 4096; idx += THREADS) {
        int m   = idx >> 12;
        int rem = idx & 4095;
        int k   = rem >> 5;
        int q   = rem & 31;
        const float* src = (m == 0) ? w2 : (m == 1) ? w3 : w4;
        float*       dst = (m == 0) ? w2s : (m == 1) ? w3s : w4s;
        reinterpret_cast<float4*>(dst)[k * 32 + (q ^ ((k >> 2) & 7))] =
            reinterpret_cast<const float4*>(src)[rem];
    }
    if (tid < 256) w1sm[tid] = w1[tid];    // plain copy: w1[c][j] rows of 512 B
    __syncthreads();

    const int warp  = tid >> 5;
    const int t     = tid & 31;
    const int pair  = warp >> 1;
    const int w     = warp & 1;
    const int barid = pair + 1;
    const int a     = t & 7;
    const int bsel  = t >> 3;

    char*  ab   = bufs + pair * 4096;
    float* dbuf = (float*)ab;
    const char* dbc = (const char*)ab;

    const int j0 = 64 * w + 4 * a + bsel;      // (j0>>2)&7 == a
    const int j1 = j0 + 32;                    // (j1>>2)&7 == a
    const int q0s  = (16 * w + a) << 4;
    const int q08s = (16 * w + a + 8) << 4;
    const int bsel4 = bsel << 2;

    int stofs[4];
    stofs[0] = ((2 * j0 + 0) ^ a) << 4;
    stofs[1] = ((2 * j0 + 1) ^ a) << 4;
    stofs[2] = ((2 * j1 + 0) ^ a) << 4;
    stofs[3] = ((2 * j1 + 1) ^ a) << 4;

    const char* w2c = (const char*)w2s;
    const char* w3c = (const char*)w3s;
    const char* w4c = (const char*)w4s;

    // Per-lane small weights for its two outputs/rows
    const float w10a = w1[j0],        w10b = w1[j1];
    const float w11a = w1[HDIM + j0], w11b = w1[HDIM + j1];
    const float b1a = b1[j0], b1b = b1[j1];
    const float b2a = b2[j0], b2b_ = b2[j1];
    const float b3a = b3[j0], b3b_ = b3[j1];
    const float b4a = b4[j0], b4b_ = b4[j1];
    const float w5a = w5[j0], w5b_ = w5[j1];
    (void)b5;

    // dx-stage task assignment (16 tasks x 2 j-halves over 32 lanes)
    const int mD  = t & 15;
    const int jh  = t >> 4;
    const int sD  = mD >> 1;
    const int cD  = mD & 1;

    const int gw = blockIdx.x * PAIRS + pair;
    const int nw = gridDim.x * PAIRS;

    for (int b = gw; b < NCH / 8; b += nw) {
        const int base = b * 8;
        float xs[8][2];
#pragma unroll
        for (int s = 0; s < 8; s++) {
            xs[s][0] = x0[(base + s) * 2 + 0];
            xs[s][1] = x0[(base + s) * 2 + 1];
        }

        float sp1[16], sp2[16], sp3[16];   // [jl*8 + s]

        for (int step = 0; step < NSTEPS; step++) {
            // ---- forward L1: 2 -> 128 (this half's 64 outputs) ----
            {
                ull hh[4][2];
#pragma unroll
                for (int p = 0; p < 4; p++)
#pragma unroll
                    for (int jl = 0; jl < 2; jl++) {
                        const float wX = jl ? w10b : w10a;
                        const float wY = jl ? w11b : w11a;
                        const float bB = jl ? b1b  : b1a;
                        float a0 = fmaf(xs[2*p  ][0], wX,
                                   fmaf(xs[2*p  ][1], wY, bB));
                        float a1 = fmaf(xs[2*p+1][0], wX,
                                   fmaf(xs[2*p+1][1], wY, bB));
                        float h0, s0, h1, s1;
                        silu_act(a0, h0, s0);
                        silu_act(a1, h1, s1);
                        sp1[jl * 8 + 2 * p]     = s0;
                        sp1[jl * 8 + 2 * p + 1] = s1;
                        hh[p][jl] = pack2(h0, h1);
                    }
                *(ulonglong2*)(ab + stofs[0]) = make_ulonglong2(hh[0][0], hh[1][0]);
                *(ulonglong2*)(ab + stofs[1]) = make_ulonglong2(hh[2][0], hh[3][0]);
                *(ulonglong2*)(ab + stofs[2]) = make_ulonglong2(hh[0][1], hh[1][1]);
                *(ulonglong2*)(ab + stofs[3]) = make_ulonglong2(hh[2][1], hh[3][1]);
                PBAR(barid);
            }

            fwd_pair<false>(w2c, ab, b2a, b2b_, sp2, 0.f, 0.f, dbuf,
                            q0s, q08s, bsel4, j0, j1, barid, stofs);
            fwd_pair<false>(w3c, ab, b3a, b3b_, sp3, 0.f, 0.f, dbuf,
                            q0s, q08s, bsel4, j0, j1, barid, stofs);
            fwd_pair<true >(w4c, ab, b4a, b4b_, sp3, w5a, w5b_, dbuf,
                            q0s, q08s, bsel4, j0, j1, barid, stofs);

            float accf[8][2];
            // d_a3 = (d_a4 @ W4^T) * silu'(a3)
            bwd_pair(w4c, dbc, j0, j1, a, barid, accf);
#pragma unroll
            for (int s = 0; s < 8; s++) {
                dbuf[s * HDIM + j0] = accf[s][0] * sp3[0 * 8 + s];
                dbuf[s * HDIM + j1] = accf[s][1] * sp3[1 * 8 + s];
            }
            PBAR(barid);
            // d_a2 = (d_a3 @ W3^T) * silu'(a2)
            bwd_pair(w3c, dbc, j0, j1, a, barid, accf);
#pragma unroll
            for (int s = 0; s < 8; s++) {
                dbuf[s * HDIM + j0] = accf[s][0] * sp2[0 * 8 + s];
                dbuf[s * HDIM + j1] = accf[s][1] * sp2[1 * 8 + s];
            }
            PBAR(barid);
            // d_a1 = (d_a2 @ W2^T) * silu'(a1) -> store d1
            bwd_pair(w2c, dbc, j0, j1, a, barid, accf);
#pragma unroll
            for (int s = 0; s < 8; s++) {
                dbuf[s * HDIM + j0] = accf[s][0] * sp1[0 * 8 + s];
                dbuf[s * HDIM + j1] = accf[s][1] * sp1[1 * 8 + s];
            }
            PBAR(barid);

            // ---- dx = d1 @ W1^T, cooperative: lane (mD, jh) does half the
            // j-range of task (sD, cD); cross-half add via shfl_xor(16).
            ull acc2 = pack2(0.0f, 0.0f);
#pragma unroll
            for (int qq = 0; qq < 16; qq++) {
                const int qb = (16 * jh + qq) << 4;
                ulonglong2 dv = *(const ulonglong2*)(dbc + sD * 512 + qb);
                ulonglong2 wv = *(const ulonglong2*)((const char*)w1sm + cD * 512 + qb);
                fma2(acc2, dv.x, wv.x); fma2(acc2, dv.y, wv.y);
            }
            float lo, hi; unpack2(acc2, lo, hi);
            float val = lo + hi;
            val += __shfl_xor_sync(0xffffffffu, val, 16);
            PBAR(barid);   // db reads done before next L1 overwrites ab

            // ---- Langevin update (identical in every lane of both halves) ----
            float fi  = (float)step;
            float eps = 10.0f * (1.0f - fi / 60.0f);
            float sq  = sqrtf(2.0f * eps);
            const float4* nzp = (const float4*)(noise + ((size_t)step * NCH + base) * 2);
            float4 n0 = nzp[0], n1 = nzp[1], n2 = nzp[2], n3 = nzp[3];
            float nzv[16] = {n0.x, n0.y, n0.z, n0.w, n1.x, n1.y, n1.z, n1.w,
                             n2.x, n2.y, n2.z, n2.w, n3.x, n3.y, n3.z, n3.w};
#pragma unroll
            for (int s = 0; s < 8; s++) {
#pragma unroll
                for (int c = 0; c < 2; c++) {
                    float dxv = __shfl_sync(0xffffffffu, val, 2 * s + c);
                    float nz  = nzv[2 * s + c];
                    float g   = fminf(fmaxf(dxv, -0.03f), 0.03f);
                    float xv  = xs[s][c] + sq * nz * 0.005f + eps * g;
                    xs[s][c]  = fminf(fmaxf(xv, -2.43f), 3.05f);
                }
            }
        }

        if (w == 0 && t < 16) {
            out[base * 2 + t] = xs[t >> 1][t & 1];
        }
    }
}

extern "C" void kernel_launch(void* const* d_in, const int* in_sizes, int n_in,
                              void* d_out, int out_size)
{
    const float* x0    = (const float*)d_in[0];
    const float* w1    = (const float*)d_in[1];
    const float* b1    = (const float*)d_in[2];
    const float* w2    = (const float*)d_in[3];
    const float* b2    = (const float*)d_in[4];
    const float* w3    = (const float*)d_in[5];
    const float* b3    = (const float*)d_in[6];
    const float* w4    = (const float*)d_in[7];
    const float* b4    = (const float*)d_in[8];
    const float* w5    = (const float*)d_in[9];
    const float* b5    = (const float*)d_in[10];
    const float* noise = (const float*)d_in[11];

    const int smemBytes = 196608 + PAIRS * 4096 + 1024;   // 222208
    cudaFuncSetAttribute(ebm_langevin_kernel,
                         cudaFuncAttributeMaxDynamicSharedMemorySize, smemBytes);

    int nsm = 148;
    cudaDeviceGetAttribute(&nsm, cudaDevAttrMultiProcessorCount, 0);

    ebm_langevin_kernel<<<nsm, THREADS, smemBytes>>>(
        x0, w1, b1, w2, b2, w3, b3, w4, b4, w5, b5, noise, (float*)d_out);
}

// round 12
// speedup vs baseline: 1.0031x; 1.0031x over previous
#include <cuda_runtime.h>
#include <math.h>

#define NCH    131072
#define NSTEPS 60
#define HDIM   128
#define THREADS 384
#define PAIRS   6

typedef unsigned long long ull;

// ---------------------------------------------------------------------------
// Packed fp32x2 helpers (sm_103a FFMA2 — only reachable via PTX f32x2 ops).
// ---------------------------------------------------------------------------
static __device__ __forceinline__ ull pack2(float lo, float hi) {
    ull r; asm("mov.b64 %0, {%1, %2};" : "=l"(r) : "f"(lo), "f"(hi)); return r;
}
static __device__ __forceinline__ void unpack2(ull v, float& lo, float& hi) {
    asm("mov.b64 {%0, %1}, %2;" : "=f"(lo), "=f"(hi) : "l"(v));
}
static __device__ __forceinline__ void fma2(ull& c, ull a, ull b) {
    asm("fma.rn.f32x2 %0, %1, %2, %0;" : "+l"(c) : "l"(a), "l"(b));
}

static __device__ __forceinline__ void silu_act(float a, float& h, float& sp) {
    float e   = __expf(-a);
    float sig = __fdividef(1.0f, 1.0f + e);
    h  = a * sig;
    sp = sig * (1.0f + a * (1.0f - sig));
}
static __device__ __forceinline__ float silu_prime(float a) {
    float e   = __expf(-a);
    float sig = __fdividef(1.0f, 1.0f + e);
    return sig * (1.0f + a * (1.0f - sig));
}

#define PBAR(id) asm volatile("bar.sync %0, 64;" :: "r"(id) : "memory")

// ---------------------------------------------------------------------------
// 12 warps = 6 warp-pairs; each pair owns 8 chains and one 4 KB buffer.
// Warp half w of a pair owns outputs/rows j0 = 64w + 4(t&7) + (t>>3),
// j1 = j0 + 32.  (j>>2)&7 == t&7 for both, so every swizzled access below is
// conflict-free per quarter-warp phase.
//
// Activations (pair-major, swizzled 16B slots): slot(k,half) = (2k+half) ^
// ((k>>2)&7); half0 = f32x2 pairs (s0,s1),(s2,s3), half1 = (s4..s7).
// Backward d-buffer: plain sample-major d[s][j] at s*512 + 4j bytes.
// Weights: quad q of row k at slot q ^ ((k>>2)&7)  (row stride 512 B).
// ---------------------------------------------------------------------------

// Forward 128->128: warp half computes its 64 outputs (2 per lane) for 8
// samples, sample-pair packed FMA2. SEED: layer 4 writes d_a4 directly.
template<bool SEED>
static __device__ __forceinline__ void fwd_pair(
    const char* __restrict__ Ws, char* __restrict__ ab,
    float ba, float bb, float* __restrict__ sp,
    float w5a, float w5b, float* __restrict__ dbuf,
    int q0s, int q08s, int bsel4, int j0, int j1, int barid,
    const int* __restrict__ stofs)
{
    ull acc[4][2];
    {
        ull bd0 = pack2(ba, ba), bd1 = pack2(bb, bb);
#pragma unroll
        for (int p = 0; p < 4; p++) { acc[p][0] = bd0; acc[p][1] = bd1; }
    }
    const char* WsB = Ws + bsel4;
#pragma unroll 1
    for (int k0 = 0; k0 < HDIM; k0 += 32) {     // swizzle period
        const char* wb = WsB + k0 * 512;
        const char* hb = ab  + k0 * 32;
#pragma unroll
        for (int kk = 0; kk < 32; kk++) {
            const int c  = (kk >> 2) & 7;        // compile-time
            const int cs = c << 4;
            float wv0 = *(const float*)(wb + kk * 512 + (q0s  ^ cs));
            float wv1 = *(const float*)(wb + kk * 512 + (q08s ^ cs));
            ull wd0 = pack2(wv0, wv0), wd1 = pack2(wv1, wv1);
            ulonglong2 hA = *(const ulonglong2*)(hb + (((2*kk    ) ^ c) << 4));
            ulonglong2 hB = *(const ulonglong2*)(hb + (((2*kk + 1) ^ c) << 4));
            fma2(acc[0][0], hA.x, wd0); fma2(acc[0][1], hA.x, wd1);
            fma2(acc[1][0], hA.y, wd0); fma2(acc[1][1], hA.y, wd1);
            fma2(acc[2][0], hB.x, wd0); fma2(acc[2][1], hB.x, wd1);
            fma2(acc[3][0], hB.y, wd0); fma2(acc[3][1], hB.y, wd1);
        }
    }
    PBAR(barid);    // both halves done reading ab before it is overwritten

    if (!SEED) {
        ull hh[4][2];
#pragma unroll
        for (int p = 0; p < 4; p++)
#pragma unroll
            for (int jl = 0; jl < 2; jl++) {
                float a0, a1; unpack2(acc[p][jl], a0, a1);
                float h0, s0, h1, s1;
                silu_act(a0, h0, s0);
                silu_act(a1, h1, s1);
                sp[jl * 8 + 2 * p]     = s0;
                sp[jl * 8 + 2 * p + 1] = s1;
                hh[p][jl] = pack2(h0, h1);
            }
        *(ulonglong2*)(ab + stofs[0]) = make_ulonglong2(hh[0][0], hh[1][0]);
        *(ulonglong2*)(ab + stofs[1]) = make_ulonglong2(hh[2][0], hh[3][0]);
        *(ulonglong2*)(ab + stofs[2]) = make_ulonglong2(hh[0][1], hh[1][1]);
        *(ulonglong2*)(ab + stofs[3]) = make_ulonglong2(hh[2][1], hh[3][1]);
        PBAR(barid);
    } else {
        // d_a4 = w5 (.) silu'(a4) -> sample-major dbuf (rows j0, j1 only)
#pragma unroll
        for (int p = 0; p < 4; p++) {
            float a0, a1, c0, c1;
            unpack2(acc[p][0], a0, a1);
            unpack2(acc[p][1], c0, c1);
            dbuf[(2*p    ) * HDIM + j0] = w5a * silu_prime(a0);
            dbuf[(2*p    ) * HDIM + j1] = w5b * silu_prime(c0);
            dbuf[(2*p + 1) * HDIM + j0] = w5a * silu_prime(a1);
            dbuf[(2*p + 1) * HDIM + j1] = w5b * silu_prime(c1);
        }
        PBAR(barid);
    }
}

// Backward through W^T: warp half computes rows j0, j1 (2 per lane), summing
// over ALL 128 j (j-packed f32x2, hsum at the end). No cross-warp reduction.
static __device__ __forceinline__ void bwd_pair(
    const char* __restrict__ Ws, const char* __restrict__ db,
    int j0, int j1, int a, int barid, float accf[8][2])
{
    ull acc[8][2];
    const ull z = pack2(0.0f, 0.0f);
#pragma unroll
    for (int s = 0; s < 8; s++) { acc[s][0] = z; acc[s][1] = z; }

    const char* wrA = Ws + j0 * 512;
    const char* wrB = Ws + j1 * 512;

#pragma unroll 1
    for (int qi = 0; qi < 8; qi++) {            // quad = 8g + qi
        const int wo   = (qi ^ a) << 4;
        const int dofs = qi << 4;
#pragma unroll
        for (int g = 0; g < 4; g++) {
            const int go = g * 128;
            ulonglong2 wA = *(const ulonglong2*)(wrA + go + wo);
            ulonglong2 wB = *(const ulonglong2*)(wrB + go + wo);
#pragma unroll
            for (int s = 0; s < 8; s++) {
                ulonglong2 dv = *(const ulonglong2*)(db + s * 512 + go + dofs);
                fma2(acc[s][0], dv.x, wA.x); fma2(acc[s][0], dv.y, wA.y);
                fma2(acc[s][1], dv.x, wB.x); fma2(acc[s][1], dv.y, wB.y);
            }
        }
    }
    PBAR(barid);    // both halves done reading db before it is overwritten

#pragma unroll
    for (int s = 0; s < 8; s++) {
        float lo, hi;
        unpack2(acc[s][0], lo, hi); accf[s][0] = lo + hi;
        unpack2(acc[s][1], lo, hi); accf[s][1] = lo + hi;
    }
}

// smem: 3 x 64KB swizzled weights + 6 pairs x 4KB buffers + 1KB w1 = 222208 B
extern "C" __global__ void __launch_bounds__(THREADS, 1)
ebm_langevin_kernel(const float* __restrict__ x0,
                    const float* __restrict__ w1, const float* __restrict__ b1,
                    const float* __restrict__ w2, const float* __restrict__ b2,
                    const float* __restrict__ w3, const float* __restrict__ b3,
                    const float* __restrict__ w4, const float* __restrict__ b4,
                    const float* __restrict__ w5, const float* __restrict__ b5,
                    const float* __restrict__ noise,
                    float* __restrict__ out)
{
    extern __shared__ float smem[];
    float* w2s  = smem;
    float* w3s  = smem + 16384;
    float* w4s  = smem + 32768;
    char*  bufs = (char*)(smem + 49152);
    float* w1sm = (float*)(bufs + PAIRS * 4096);   // 256 floats

    const int tid = threadIdx.x;

    // Cooperative swizzled weight load: quad q of row k -> slot q ^ ((k>>2)&7).
    for (int idx = tid; idx < 3 * 4096; idx += THREADS) {
        int m   = idx >> 12;
        int rem = idx & 4095;
        int k   = rem >> 5;
        int q   = rem & 31;
        const float* src = (m == 0) ? w2 : (m == 1) ? w3 : w4;
        float*       dst = (m == 0) ? w2s : (m == 1) ? w3s : w4s;
        reinterpret_cast<float4*>(dst)[k * 32 + (q ^ ((k >> 2) & 7))] =
            reinterpret_cast<const float4*>(src)[rem];
    }
    if (tid < 256) w1sm[tid] = w1[tid];    // plain copy: w1[c][j] rows of 512 B
    __syncthreads();

    const int warp  = tid >> 5;
    const int t     = tid & 31;
    const int pair  = warp >> 1;
    const int w     = warp & 1;
    const int barid = pair + 1;
    const int a     = t & 7;
    const int bsel  = t >> 3;

    char*  ab   = bufs + pair * 4096;
    float* dbuf = (float*)ab;
    const char* dbc = (const char*)ab;

    const int j0 = 64 * w + 4 * a + bsel;      // (j0>>2)&7 == a
    const int j1 = j0 + 32;                    // (j1>>2)&7 == a
    const int q0s  = (16 * w + a) << 4;
    const int q08s = (16 * w + a + 8) << 4;
    const int bsel4 = bsel << 2;

    int stofs[4];
    stofs[0] = ((2 * j0 + 0) ^ a) << 4;
    stofs[1] = ((2 * j0 + 1) ^ a) << 4;
    stofs[2] = ((2 * j1 + 0) ^ a) << 4;
    stofs[3] = ((2 * j1 + 1) ^ a) << 4;

    const char* w2c = (const char*)w2s;
    const char* w3c = (const char*)w3s;
    const char* w4c = (const char*)w4s;

    // Per-lane small weights for its two outputs/rows
    const float w10a = w1[j0],        w10b = w1[j1];
    const float w11a = w1[HDIM + j0], w11b = w1[HDIM + j1];
    const float b1a = b1[j0], b1b = b1[j1];
    const float b2a = b2[j0], b2b_ = b2[j1];
    const float b3a = b3[j0], b3b_ = b3[j1];
    const float b4a = b4[j0], b4b_ = b4[j1];
    const float w5a = w5[j0], w5b_ = w5[j1];
    (void)b5;

    // dx-stage task assignment (16 tasks x 2 j-halves over 32 lanes)
    const int mD  = t & 15;
    const int jh  = t >> 4;
    const int sD  = mD >> 1;
    const int cD  = mD & 1;

    const int gw = blockIdx.x * PAIRS + pair;
    const int nw = gridDim.x * PAIRS;

    for (int b = gw; b < NCH / 8; b += nw) {
        const int base = b * 8;
        float xs[8][2];
#pragma unroll
        for (int s = 0; s < 8; s++) {
            xs[s][0] = x0[(base + s) * 2 + 0];
            xs[s][1] = x0[(base + s) * 2 + 1];
        }

        float sp1[16], sp2[16], sp3[16];   // [jl*8 + s]

        for (int step = 0; step < NSTEPS; step++) {
            // ---- forward L1: 2 -> 128 (this half's 64 outputs) ----
            {
                ull hh[4][2];
#pragma unroll
                for (int p = 0; p < 4; p++)
#pragma unroll
                    for (int jl = 0; jl < 2; jl++) {
                        const float wX = jl ? w10b : w10a;
                        const float wY = jl ? w11b : w11a;
                        const float bB = jl ? b1b  : b1a;
                        float a0 = fmaf(xs[2*p  ][0], wX,
                                   fmaf(xs[2*p  ][1], wY, bB));
                        float a1 = fmaf(xs[2*p+1][0], wX,
                                   fmaf(xs[2*p+1][1], wY, bB));
                        float h0, s0, h1, s1;
                        silu_act(a0, h0, s0);
                        silu_act(a1, h1, s1);
                        sp1[jl * 8 + 2 * p]     = s0;
                        sp1[jl * 8 + 2 * p + 1] = s1;
                        hh[p][jl] = pack2(h0, h1);
                    }
                *(ulonglong2*)(ab + stofs[0]) = make_ulonglong2(hh[0][0], hh[1][0]);
                *(ulonglong2*)(ab + stofs[1]) = make_ulonglong2(hh[2][0], hh[3][0]);
                *(ulonglong2*)(ab + stofs[2]) = make_ulonglong2(hh[0][1], hh[1][1]);
                *(ulonglong2*)(ab + stofs[3]) = make_ulonglong2(hh[2][1], hh[3][1]);
                PBAR(barid);
            }

            fwd_pair<false>(w2c, ab, b2a, b2b_, sp2, 0.f, 0.f, dbuf,
                            q0s, q08s, bsel4, j0, j1, barid, stofs);
            fwd_pair<false>(w3c, ab, b3a, b3b_, sp3, 0.f, 0.f, dbuf,
                            q0s, q08s, bsel4, j0, j1, barid, stofs);
            fwd_pair<true >(w4c, ab, b4a, b4b_, sp3, w5a, w5b_, dbuf,
                            q0s, q08s, bsel4, j0, j1, barid, stofs);

            float accf[8][2];
            // d_a3 = (d_a4 @ W4^T) * silu'(a3)
            bwd_pair(w4c, dbc, j0, j1, a, barid, accf);
#pragma unroll
            for (int s = 0; s < 8; s++) {
                dbuf[s * HDIM + j0] = accf[s][0] * sp3[0 * 8 + s];
                dbuf[s * HDIM + j1] = accf[s][1] * sp3[1 * 8 + s];
            }
            PBAR(barid);
            // d_a2 = (d_a3 @ W3^T) * silu'(a2)
            bwd_pair(w3c, dbc, j0, j1, a, barid, accf);
#pragma unroll
            for (int s = 0; s < 8; s++) {
                dbuf[s * HDIM + j0] = accf[s][0] * sp2[0 * 8 + s];
                dbuf[s * HDIM + j1] = accf[s][1] * sp2[1 * 8 + s];
            }
            PBAR(barid);
            // d_a1 = (d_a2 @ W2^T) * silu'(a1) -> store d1
            bwd_pair(w2c, dbc, j0, j1, a, barid, accf);
#pragma unroll
            for (int s = 0; s < 8; s++) {
                dbuf[s * HDIM + j0] = accf[s][0] * sp1[0 * 8 + s];
                dbuf[s * HDIM + j1] = accf[s][1] * sp1[1 * 8 + s];
            }
            PBAR(barid);

            // ---- dx = d1 @ W1^T, cooperative: lane (mD, jh) does half the
            // j-range of task (sD, cD); cross-half add via shfl_xor(16).
            ull acc2 = pack2(0.0f, 0.0f);
#pragma unroll
            for (int qq = 0; qq < 16; qq++) {
                const int qb = (16 * jh + qq) << 4;
                ulonglong2 dv = *(const ulonglong2*)(dbc + sD * 512 + qb);
                ulonglong2 wv = *(const ulonglong2*)((const char*)w1sm + cD * 512 + qb);
                fma2(acc2, dv.x, wv.x); fma2(acc2, dv.y, wv.y);
            }
            float lo, hi; unpack2(acc2, lo, hi);
            float val = lo + hi;
            val += __shfl_xor_sync(0xffffffffu, val, 16);
            PBAR(barid);   // db reads done before next L1 overwrites ab

            // ---- Langevin update (identical in every lane of both halves) ----
            float fi  = (float)step;
            float eps = 10.0f * (1.0f - fi / 60.0f);
            float sq  = sqrtf(2.0f * eps);
            const float4* nzp = (const float4*)(noise + ((size_t)step * NCH + base) * 2);
            float4 n0 = nzp[0], n1 = nzp[1], n2 = nzp[2], n3 = nzp[3];
            float nzv[16] = {n0.x, n0.y, n0.z, n0.w, n1.x, n1.y, n1.z, n1.w,
                             n2.x, n2.y, n2.z, n2.w, n3.x, n3.y, n3.z, n3.w};
#pragma unroll
            for (int s = 0; s < 8; s++) {
#pragma unroll
                for (int c = 0; c < 2; c++) {
                    float dxv = __shfl_sync(0xffffffffu, val, 2 * s + c);
                    float nz  = nzv[2 * s + c];
                    float g   = fminf(fmaxf(dxv, -0.03f), 0.03f);
                    float xv  = xs[s][c] + sq * nz * 0.005f + eps * g;
                    xs[s][c]  = fminf(fmaxf(xv, -2.43f), 3.05f);
                }
            }
        }

        if (w == 0 && t < 16) {
            out[base * 2 + t] = xs[t >> 1][t & 1];
        }
    }
}

extern "C" void kernel_launch(void* const* d_in, const int* in_sizes, int n_in,
                              void* d_out, int out_size)
{
    const float* x0    = (const float*)d_in[0];
    const float* w1    = (const float*)d_in[1];
    const float* b1    = (const float*)d_in[2];
    const float* w2    = (const float*)d_in[3];
    const float* b2    = (const float*)d_in[4];
    const float* w3    = (const float*)d_in[5];
    const float* b3    = (const float*)d_in[6];
    const float* w4    = (const float*)d_in[7];
    const float* b4    = (const float*)d_in[8];
    const float* w5    = (const float*)d_in[9];
    const float* b5    = (const float*)d_in[10];
    const float* noise = (const float*)d_in[11];

    const int smemBytes = 196608 + PAIRS * 4096 + 1024;   // 222208
    cudaFuncSetAttribute(ebm_langevin_kernel,
                         cudaFuncAttributeMaxDynamicSharedMemorySize, smemBytes);

    int nsm = 148;
    cudaDeviceGetAttribute(&nsm, cudaDevAttrMultiProcessorCount, 0);

    ebm_langevin_kernel<<<nsm, THREADS, smemBytes>>>(
        x0, w1, b1, w2, b2, w3, b3, w4, b4, w5, b5, noise, (float*)d_out);
}

// round 13
// speedup vs baseline: 1.1405x; 1.1370x over previous
#include <cuda_runtime.h>
#include <math.h>

#define NCH    131072
#define NSTEPS 60
#define HDIM   128

typedef unsigned long long ull;

// ---------------------------------------------------------------------------
// Packed fp32x2 helpers (sm_103a FFMA2 — only reachable via PTX f32x2 ops).
// ---------------------------------------------------------------------------
static __device__ __forceinline__ ull pack2(float lo, float hi) {
    ull r; asm("mov.b64 %0, {%1, %2};" : "=l"(r) : "f"(lo), "f"(hi)); return r;
}
static __device__ __forceinline__ void unpack2(ull v, float& lo, float& hi) {
    asm("mov.b64 {%0, %1}, %2;" : "=f"(lo), "=f"(hi) : "l"(v));
}
static __device__ __forceinline__ void fma2(ull& c, ull a, ull b) {
    asm("fma.rn.f32x2 %0, %1, %2, %0;" : "+l"(c) : "l"(a), "l"(b));
}

static __device__ __forceinline__ float4 ld4(const float* p) {
    return *reinterpret_cast<const float4*>(p);
}
static __device__ __forceinline__ void st4(float* p, float4 v) {
    *reinterpret_cast<float4*>(p) = v;
}

static __device__ __forceinline__ void silu_act(float a, float& h, float& sp) {
    float e   = __expf(-a);
    float sig = __fdividef(1.0f, 1.0f + e);
    h  = a * sig;
    sp = sig * (1.0f + a * (1.0f - sig));
}
static __device__ __forceinline__ float silu_prime(float a) {
    float e   = __expf(-a);
    float sig = __fdividef(1.0f, 1.0f + e);
    return sig * (1.0f + a * (1.0f - sig));
}

// ---------------------------------------------------------------------------
// Per-warp 4 KB buffer, aliased between phases.
//
// Forward activations (pair-major, swizzled 16B slots):
//   slot(k, half) = (2k + half) ^ ((k>>2)&7)   (byte addr = slot*16)
//   half 0 holds f32x2 pairs (s0,s1),(s2,s3); half 1 holds (s4,s5),(s6,s7).
//   Writers: lane t owns k = 4t+i -> conflict-free ST.128.
//   Readers: 2x LDS.128 broadcast per k, compile-time offsets.
//
// Backward d-buffer (plain sample-major): d[s][j] at s*512 + 4j bytes.
//
// Weights (shared, 3 x 64 KB): quad q of row k at 16B slot q ^ ((k>>2)&7).
//   fwd reads quad t of row k; bwd reads rows 4t+i quad-wise. Both patterns
//   give distinct (t&7) per 8-lane LDS.128 phase -> conflict-free.
// ---------------------------------------------------------------------------

// Forward 128->128, 8 samples, sample-pair-packed FMA2; weights duplicated
// (w,w) via register packs. FMA2 emission order keeps the shared h operand in
// the SAME source slot for 4 consecutive instructions -> operand-reuse cache
// drops the RF read (rt 2 instead of 3). sp kept fp32: sp[i*8+s].
// SEED=true (layer 4): skip h store; write d_a4 = w5 (.) silu'(a4) into dbuf.
template<bool SEED>
static __device__ __forceinline__ void fwd8(const char* __restrict__ Ws,
                                            char* __restrict__ ab,
                                            float4 bv, float* __restrict__ sp,
                                            int t, const int* stofs,
                                            float4 w5v, float* __restrict__ dbuf)
{
    ull acc[4][4];
    {
        ull bd0 = pack2(bv.x, bv.x), bd1 = pack2(bv.y, bv.y);
        ull bd2 = pack2(bv.z, bv.z), bd3 = pack2(bv.w, bv.w);
#pragma unroll
        for (int p = 0; p < 4; p++) {
            acc[p][0] = bd0; acc[p][1] = bd1; acc[p][2] = bd2; acc[p][3] = bd3;
        }
    }
    const int t16 = t << 4;
#pragma unroll 1
    for (int k0 = 0; k0 < HDIM; k0 += 32) {   // swizzle period
        const char* wb = Ws + k0 * 512;
        const char* hb = ab + k0 * 32;
#pragma unroll
        for (int kk = 0; kk < 32; kk++) {
            const int c = (kk >> 2) & 7;      // compile-time
            float4 w = *(const float4*)(wb + kk * 512 + (t16 ^ (c << 4)));
            ull wd0 = pack2(w.x, w.x), wd1 = pack2(w.y, w.y);
            ull wd2 = pack2(w.z, w.z), wd3 = pack2(w.w, w.w);
            ulonglong2 hA = *(const ulonglong2*)(hb + (((2*kk    ) ^ c) << 4));
            ulonglong2 hB = *(const ulonglong2*)(hb + (((2*kk + 1) ^ c) << 4));
            // 4-consecutive runs sharing the a-operand (reuse-friendly)
            fma2(acc[0][0], hA.x, wd0); fma2(acc[0][1], hA.x, wd1);
            fma2(acc[0][2], hA.x, wd2); fma2(acc[0][3], hA.x, wd3);
            fma2(acc[1][0], hA.y, wd0); fma2(acc[1][1], hA.y, wd1);
            fma2(acc[1][2], hA.y, wd2); fma2(acc[1][3], hA.y, wd3);
            fma2(acc[2][0], hB.x, wd0); fma2(acc[2][1], hB.x, wd1);
            fma2(acc[2][2], hB.x, wd2); fma2(acc[2][3], hB.x, wd3);
            fma2(acc[3][0], hB.y, wd0); fma2(acc[3][1], hB.y, wd1);
            fma2(acc[3][2], hB.y, wd2); fma2(acc[3][3], hB.y, wd3);
        }
    }
    __syncwarp();   // everyone done reading ab (may be overwritten below)

    if (!SEED) {
        ull hp[4][4];
#pragma unroll
        for (int p = 0; p < 4; p++)
#pragma unroll
            for (int i = 0; i < 4; i++) {
                float a0, a1; unpack2(acc[p][i], a0, a1);
                float h0, s0, h1, s1;
                silu_act(a0, h0, s0);
                silu_act(a1, h1, s1);
                sp[i * 8 + 2 * p]     = s0;
                sp[i * 8 + 2 * p + 1] = s1;
                hp[p][i] = pack2(h0, h1);
            }
#pragma unroll
        for (int i = 0; i < 4; i++) {
            *(ulonglong2*)(ab + stofs[2*i+0]) = make_ulonglong2(hp[0][i], hp[1][i]);
            *(ulonglong2*)(ab + stofs[2*i+1]) = make_ulonglong2(hp[2][i], hp[3][i]);
        }
        __syncwarp();
    } else {
        // d_a4 = w5 (.) silu'(a4), stored sample-major; sp4 never materialized.
        float w5a[4] = {w5v.x, w5v.y, w5v.z, w5v.w};
#pragma unroll
        for (int p = 0; p < 4; p++) {
            float d0[4], d1[4];
#pragma unroll
            for (int i = 0; i < 4; i++) {
                float a0, a1; unpack2(acc[p][i], a0, a1);
                d0[i] = w5a[i] * silu_prime(a0);
                d1[i] = w5a[i] * silu_prime(a1);
            }
            st4(dbuf + (2*p    ) * HDIM + 4 * t, make_float4(d0[0], d0[1], d0[2], d0[3]));
            st4(dbuf + (2*p + 1) * HDIM + 4 * t, make_float4(d1[0], d1[1], d1[2], d1[3]));
        }
        __syncwarp();
    }
}

// Backward through W^T, 8 samples, j-packed (even/odd j in the f32x2 lanes).
// accf[s][i] = sum_j d[s][j] * W[4t+i][j].
// FMA2 emission: dv.x is the a-operand of 4 CONSECUTIVE instructions, then
// dv.y of the next 4 (operand-reuse cache drops an RF read -> rt 2, not 3).
// Each accumulator still receives its x-term before its y-term, so the
// per-accumulator addition order is unchanged -> bit-identical to R8.
static __device__ __forceinline__ void bwd8(const char* __restrict__ Ws,
                                            const char* __restrict__ db,
                                            int t, int t7, float accf[8][4])
{
    ull acc[8][4];
    const ull z = pack2(0.0f, 0.0f);
#pragma unroll
    for (int s = 0; s < 8; s++)
#pragma unroll
        for (int i = 0; i < 4; i++) acc[s][i] = z;

    const char* wr0 = Ws + (4 * t + 0) * 512;
    const char* wr1 = Ws + (4 * t + 1) * 512;
    const char* wr2 = Ws + (4 * t + 2) * 512;
    const char* wr3 = Ws + (4 * t + 3) * 512;

#pragma unroll 1
    for (int qi = 0; qi < 8; qi++) {          // q = 8g + qi covers all 32 quads
        const int wo   = (qi ^ t7) << 4;
        const int dofs = qi << 4;
#pragma unroll
        for (int g = 0; g < 4; g++) {
            const int go = g * 128;
            ulonglong2 w0 = *(const ulonglong2*)(wr0 + go + wo);
            ulonglong2 w1 = *(const ulonglong2*)(wr1 + go + wo);
            ulonglong2 w2 = *(const ulonglong2*)(wr2 + go + wo);
            ulonglong2 w3 = *(const ulonglong2*)(wr3 + go + wo);
#pragma unroll
            for (int s = 0; s < 8; s++) {
                ulonglong2 dv = *(const ulonglong2*)(db + s * 512 + go + dofs);
                fma2(acc[s][0], dv.x, w0.x);
                fma2(acc[s][1], dv.x, w1.x);
                fma2(acc[s][2], dv.x, w2.x);
                fma2(acc[s][3], dv.x, w3.x);
                fma2(acc[s][0], dv.y, w0.y);
                fma2(acc[s][1], dv.y, w1.y);
                fma2(acc[s][2], dv.y, w2.y);
                fma2(acc[s][3], dv.y, w3.y);
            }
        }
    }
    __syncwarp();   // everyone done reading db

#pragma unroll
    for (int s = 0; s < 8; s++)
#pragma unroll
        for (int i = 0; i < 4; i++) {
            float lo, hi; unpack2(acc[s][i], lo, hi);
            accf[s][i] = lo + hi;
        }
}

// smem: 3 x 64KB swizzled weights + 8 warps x 4KB buffers = 229376 B
extern "C" __global__ void __launch_bounds__(256, 1)
ebm_langevin_kernel(const float* __restrict__ x0,
                    const float* __restrict__ w1, const float* __restrict__ b1,
                    const float* __restrict__ w2, const float* __restrict__ b2,
                    const float* __restrict__ w3, const float* __restrict__ b3,
                    const float* __restrict__ w4, const float* __restrict__ b4,
                    const float* __restrict__ w5, const float* __restrict__ b5,
                    const float* __restrict__ noise,
                    float* __restrict__ out)
{
    extern __shared__ float smem[];
    float* w2s = smem;
    float* w3s = smem + 16384;
    float* w4s = smem + 32768;
    char*  bufs = (char*)(smem + 49152);

    const int tid = threadIdx.x;

    // Cooperative swizzled weight load: quad q of row k -> slot q ^ ((k>>2)&7).
    for (int idx = tid; idx < 3 * 4096; idx += 256) {
        int m   = idx >> 12;
        int rem = idx & 4095;
        int k   = rem >> 5;
        int q   = rem & 31;
        const float* src = (m == 0) ? w2 : (m == 1) ? w3 : w4;
        float*       dst = (m == 0) ? w2s : (m == 1) ? w3s : w4s;
        reinterpret_cast<float4*>(dst)[k * 32 + (q ^ ((k >> 2) & 7))] =
            reinterpret_cast<const float4*>(src)[rem];
    }
    __syncthreads();

    const int warp = tid >> 5;
    const int t    = tid & 31;
    const int t7   = t & 7;
    char*  ab   = bufs + warp * 4096;
    float* dbuf = (float*)ab;

    const char* w2c = (const char*)w2s;
    const char* w3c = (const char*)w3s;
    const char* w4c = (const char*)w4s;

    // Per-lane activation-store offsets (conflict-free swizzled ST.128):
    // k = 4t+i, half -> byte ((8t + 2i + half) ^ (t&7)) * 16
    int stofs[8];
#pragma unroll
    for (int i = 0; i < 4; i++)
#pragma unroll
        for (int half = 0; half < 2; half++)
            stofs[2 * i + half] = (t << 7) + ((((i << 1) | half) ^ t7) << 4);

    const int gw = blockIdx.x * 8 + warp;
    const int nw = gridDim.x * 8;

    const float4 w1r0 = ld4(w1 + 4 * t);
    const float4 w1r1 = ld4(w1 + HDIM + 4 * t);
    const float4 b1v  = ld4(b1 + 4 * t);
    const float4 b2v  = ld4(b2 + 4 * t);
    const float4 b3v  = ld4(b3 + 4 * t);
    const float4 b4v  = ld4(b4 + 4 * t);
    const float4 w5v  = ld4(w5 + 4 * t);
    (void)b5;
    float w1A[4] = {w1r0.x, w1r0.y, w1r0.z, w1r0.w};
    float w1B[4] = {w1r1.x, w1r1.y, w1r1.z, w1r1.w};
    float bb1[4] = {b1v.x,  b1v.y,  b1v.z,  b1v.w};

    for (int b = gw; b < NCH / 8; b += nw) {
        const int base = b * 8;
        float xs[8][2];
#pragma unroll
        for (int s = 0; s < 8; s++) {
            xs[s][0] = x0[(base + s) * 2 + 0];
            xs[s][1] = x0[(base + s) * 2 + 1];
        }

        // fp32 silu' caches: sp[i*8 + s], i = output quad-lane, s = sample.
        float sp1[32], sp2[32], sp3[32];

        for (int step = 0; step < NSTEPS; step++) {
            // ---- forward L1: 2 -> 128 (writes pair-major activation buf) ----
            {
                ull hp[4][4];
#pragma unroll
                for (int p = 0; p < 4; p++)
#pragma unroll
                    for (int i = 0; i < 4; i++) {
                        float a0 = fmaf(xs[2*p  ][0], w1A[i],
                                   fmaf(xs[2*p  ][1], w1B[i], bb1[i]));
                        float a1 = fmaf(xs[2*p+1][0], w1A[i],
                                   fmaf(xs[2*p+1][1], w1B[i], bb1[i]));
                        float h0, s0, h1, s1;
                        silu_act(a0, h0, s0);
                        silu_act(a1, h1, s1);
                        sp1[i * 8 + 2 * p]     = s0;
                        sp1[i * 8 + 2 * p + 1] = s1;
                        hp[p][i] = pack2(h0, h1);
                    }
#pragma unroll
                for (int i = 0; i < 4; i++) {
                    *(ulonglong2*)(ab + stofs[2*i+0]) = make_ulonglong2(hp[0][i], hp[1][i]);
                    *(ulonglong2*)(ab + stofs[2*i+1]) = make_ulonglong2(hp[2][i], hp[3][i]);
                }
                __syncwarp();
            }

            fwd8<false>(w2c, ab, b2v, sp2, t, stofs, w5v, dbuf);  // h1 -> h2
            fwd8<false>(w3c, ab, b3v, sp3, t, stofs, w5v, dbuf);  // h2 -> h3
            fwd8<true >(w4c, ab, b4v, sp3 /*unused*/, t, stofs, w5v, dbuf); // seed d_a4

            float accf[8][4];
            // d_a3 = (d_a4 @ W4^T) * silu'(a3)
            bwd8(w4c, (const char*)dbuf, t, t7, accf);
#pragma unroll
            for (int s = 0; s < 8; s++) {
                st4(dbuf + s * HDIM + 4 * t,
                    make_float4(accf[s][0] * sp3[0 * 8 + s],
                                accf[s][1] * sp3[1 * 8 + s],
                                accf[s][2] * sp3[2 * 8 + s],
                                accf[s][3] * sp3[3 * 8 + s]));
            }
            __syncwarp();
            // d_a2 = (d_a3 @ W3^T) * silu'(a2)
            bwd8(w3c, (const char*)dbuf, t, t7, accf);
#pragma unroll
            for (int s = 0; s < 8; s++) {
                st4(dbuf + s * HDIM + 4 * t,
                    make_float4(accf[s][0] * sp2[0 * 8 + s],
                                accf[s][1] * sp2[1 * 8 + s],
                                accf[s][2] * sp2[2 * 8 + s],
                                accf[s][3] * sp2[3 * 8 + s]));
            }
            __syncwarp();
            // d_a1 = (d_a2 @ W2^T) * silu'(a1) ; dx = d_a1 @ W1^T
            bwd8(w2c, (const char*)dbuf, t, t7, accf);

            float pdx[8][2];
#pragma unroll
            for (int s = 0; s < 8; s++) {
                float d0 = accf[s][0] * sp1[0 * 8 + s];
                float d1 = accf[s][1] * sp1[1 * 8 + s];
                float d2 = accf[s][2] * sp1[2 * 8 + s];
                float d3 = accf[s][3] * sp1[3 * 8 + s];
                pdx[s][0] = fmaf(d0, w1A[0], fmaf(d1, w1A[1],
                            fmaf(d2, w1A[2], d3 * w1A[3])));
                pdx[s][1] = fmaf(d0, w1B[0], fmaf(d1, w1B[1],
                            fmaf(d2, w1B[2], d3 * w1B[3])));
            }
            // butterfly reduce -> every lane holds full dx for all 8 samples
#pragma unroll
            for (int off = 16; off > 0; off >>= 1) {
#pragma unroll
                for (int s = 0; s < 8; s++) {
                    pdx[s][0] += __shfl_xor_sync(0xffffffffu, pdx[s][0], off);
                    pdx[s][1] += __shfl_xor_sync(0xffffffffu, pdx[s][1], off);
                }
            }

            // ---- Langevin update (replicated identically in all lanes) ----
            float fi  = (float)step;
            float eps = 10.0f * (1.0f - fi / 60.0f);
            float sq  = sqrtf(2.0f * eps);
            const float4* nzp = (const float4*)(noise + ((size_t)step * NCH + base) * 2);
            float4 n0 = nzp[0], n1 = nzp[1], n2 = nzp[2], n3 = nzp[3];
            float nzv[16] = {n0.x, n0.y, n0.z, n0.w, n1.x, n1.y, n1.z, n1.w,
                             n2.x, n2.y, n2.z, n2.w, n3.x, n3.y, n3.z, n3.w};
#pragma unroll
            for (int s = 0; s < 8; s++) {
#pragma unroll
                for (int c = 0; c < 2; c++) {
                    float nz = nzv[2 * s + c];
                    float g  = fminf(fmaxf(pdx[s][c], -0.03f), 0.03f);
                    float xv = xs[s][c] + sq * nz * 0.005f + eps * g;
                    xs[s][c] = fminf(fmaxf(xv, -2.43f), 3.05f);
                }
            }
            // next L1 store is safe: bwd8 already syncwarp'd after its reads
        }

        if (t < 16) {
            out[base * 2 + t] = xs[t >> 1][t & 1];
        }
    }
}

extern "C" void kernel_launch(void* const* d_in, const int* in_sizes, int n_in,
                              void* d_out, int out_size)
{
    const float* x0    = (const float*)d_in[0];
    const float* w1    = (const float*)d_in[1];
    const float* b1    = (const float*)d_in[2];
    const float* w2    = (const float*)d_in[3];
    const float* b2    = (const float*)d_in[4];
    const float* w3    = (const float*)d_in[5];
    const float* b3    = (const float*)d_in[6];
    const float* w4    = (const float*)d_in[7];
    const float* b4    = (const float*)d_in[8];
    const float* w5    = (const float*)d_in[9];
    const float* b5    = (const float*)d_in[10];
    const float* noise = (const float*)d_in[11];

    const int smemBytes = 57344 * (int)sizeof(float);   // 229376
    cudaFuncSetAttribute(ebm_langevin_kernel,
                         cudaFuncAttributeMaxDynamicSharedMemorySize, smemBytes);

    int nsm = 148;
    cudaDeviceGetAttribute(&nsm, cudaDevAttrMultiProcessorCount, 0);

    ebm_langevin_kernel<<<nsm, 256, smemBytes>>>(
        x0, w1, b1, w2, b2, w3, b3, w4, b4, w5, b5, noise, (float*)d_out);
}

// round 14
// speedup vs baseline: 1.1481x; 1.0067x over previous
#include <cuda_runtime.h>
#include <math.h>

#define NCH    131072
#define NSTEPS 60
#define HDIM   128

typedef unsigned long long ull;

// ---------------------------------------------------------------------------
// Packed fp32x2 helpers (sm_103a FFMA2 — only reachable via PTX f32x2 ops).
// FFMA2 reads 3x64-bit operands -> 3 even + 3 odd bank registers -> rt 3
// (RF-banking law). Scalar FFMA is rt 2. The fma PIPE accepts 1 op / 2 cyc,
// so a mixed F2+F stream reaches ~0.8 MACs/cyc vs 0.67 for pure FFMA2.
// Samples 0-5 stay FFMA2-packed; samples 6-7 run scalar FFMA.
// ---------------------------------------------------------------------------
static __device__ __forceinline__ ull pack2(float lo, float hi) {
    ull r; asm("mov.b64 %0, {%1, %2};" : "=l"(r) : "f"(lo), "f"(hi)); return r;
}
static __device__ __forceinline__ void unpack2(ull v, float& lo, float& hi) {
    asm("mov.b64 {%0, %1}, %2;" : "=f"(lo), "=f"(hi) : "l"(v));
}
static __device__ __forceinline__ void fma2(ull& c, ull a, ull b) {
    asm("fma.rn.f32x2 %0, %1, %2, %0;" : "+l"(c) : "l"(a), "l"(b));
}

static __device__ __forceinline__ float4 ld4(const float* p) {
    return *reinterpret_cast<const float4*>(p);
}
static __device__ __forceinline__ void st4(float* p, float4 v) {
    *reinterpret_cast<float4*>(p) = v;
}

static __device__ __forceinline__ void silu_act(float a, float& h, float& sp) {
    float e   = __expf(-a);
    float sig = __fdividef(1.0f, 1.0f + e);
    h  = a * sig;
    sp = sig * (1.0f + a * (1.0f - sig));
}
static __device__ __forceinline__ float silu_prime(float a) {
    float e   = __expf(-a);
    float sig = __fdividef(1.0f, 1.0f + e);
    return sig * (1.0f + a * (1.0f - sig));
}

// ---------------------------------------------------------------------------
// Layouts identical to R8/R13 (validated):
// Activations pair-major swizzled 16B slots: slot(k,half)=(2k+half)^((k>>2)&7);
// half0 = f32x2 pairs (s0,s1),(s2,s3); half1 = (s4,s5),(s6,s7).
// Backward d-buffer sample-major: d[s][j] at s*512 + 4j.
// Weights: quad q of row k at slot q ^ ((k>>2)&7), row stride 512 B.
// ---------------------------------------------------------------------------

// Forward 128->128, 8 samples. Samples 0-5: sample-pair FFMA2 (weights packed
// (w,w) via mov.b64). Samples 6-7: scalar FFMA on the same loaded registers.
// SEED=true (layer 4): skip h store; write d_a4 = w5 (.) silu'(a4) into dbuf.
template<bool SEED>
static __device__ __forceinline__ void fwd8(const char* __restrict__ Ws,
                                            char* __restrict__ ab,
                                            float4 bv, float* __restrict__ sp,
                                            int t, const int* stofs,
                                            float4 w5v, float* __restrict__ dbuf)
{
    ull  acc[3][4];      // sample-pairs (s0,s1),(s2,s3),(s4,s5) x outputs
    float sacc[2][4];    // samples s6, s7 (scalar) x outputs
    {
        ull bd0 = pack2(bv.x, bv.x), bd1 = pack2(bv.y, bv.y);
        ull bd2 = pack2(bv.z, bv.z), bd3 = pack2(bv.w, bv.w);
#pragma unroll
        for (int p = 0; p < 3; p++) {
            acc[p][0] = bd0; acc[p][1] = bd1; acc[p][2] = bd2; acc[p][3] = bd3;
        }
#pragma unroll
        for (int si = 0; si < 2; si++) {
            sacc[si][0] = bv.x; sacc[si][1] = bv.y;
            sacc[si][2] = bv.z; sacc[si][3] = bv.w;
        }
    }
    const int t16 = t << 4;
#pragma unroll 1
    for (int k0 = 0; k0 < HDIM; k0 += 32) {   // swizzle period
        const char* wb = Ws + k0 * 512;
        const char* hb = ab + k0 * 32;
#pragma unroll
        for (int kk = 0; kk < 32; kk++) {
            const int c = (kk >> 2) & 7;      // compile-time
            float4 w = *(const float4*)(wb + kk * 512 + (t16 ^ (c << 4)));
            ull wd0 = pack2(w.x, w.x), wd1 = pack2(w.y, w.y);
            ull wd2 = pack2(w.z, w.z), wd3 = pack2(w.w, w.w);
            ulonglong2 hA = *(const ulonglong2*)(hb + (((2*kk    ) ^ c) << 4));
            float4     hB = *(const float4*)   (hb + (((2*kk + 1) ^ c) << 4));
            ull hp45 = pack2(hB.x, hB.y);     // (s4,s5) pair (reg-aliased)
            // packed pairs (12 F2) interleaved with scalar s6,s7 (8 F)
            fma2(acc[0][0], hA.x, wd0); fma2(acc[0][1], hA.x, wd1);
            sacc[0][0] = fmaf(hB.z, w.x, sacc[0][0]);
            sacc[1][0] = fmaf(hB.w, w.x, sacc[1][0]);
            fma2(acc[0][2], hA.x, wd2); fma2(acc[0][3], hA.x, wd3);
            sacc[0][1] = fmaf(hB.z, w.y, sacc[0][1]);
            sacc[1][1] = fmaf(hB.w, w.y, sacc[1][1]);
            fma2(acc[1][0], hA.y, wd0); fma2(acc[1][1], hA.y, wd1);
            sacc[0][2] = fmaf(hB.z, w.z, sacc[0][2]);
            sacc[1][2] = fmaf(hB.w, w.z, sacc[1][2]);
            fma2(acc[1][2], hA.y, wd2); fma2(acc[1][3], hA.y, wd3);
            sacc[0][3] = fmaf(hB.z, w.w, sacc[0][3]);
            sacc[1][3] = fmaf(hB.w, w.w, sacc[1][3]);
            fma2(acc[2][0], hp45, wd0); fma2(acc[2][1], hp45, wd1);
            fma2(acc[2][2], hp45, wd2); fma2(acc[2][3], hp45, wd3);
        }
    }
    __syncwarp();   // everyone done reading ab (may be overwritten below)

    if (!SEED) {
        ull hp[4][4];
#pragma unroll
        for (int p = 0; p < 3; p++)
#pragma unroll
            for (int i = 0; i < 4; i++) {
                float a0, a1; unpack2(acc[p][i], a0, a1);
                float h0, s0, h1, s1;
                silu_act(a0, h0, s0);
                silu_act(a1, h1, s1);
                sp[i * 8 + 2 * p]     = s0;
                sp[i * 8 + 2 * p + 1] = s1;
                hp[p][i] = pack2(h0, h1);
            }
#pragma unroll
        for (int i = 0; i < 4; i++) {
            float h6, s6, h7, s7;
            silu_act(sacc[0][i], h6, s6);
            silu_act(sacc[1][i], h7, s7);
            sp[i * 8 + 6] = s6;
            sp[i * 8 + 7] = s7;
            hp[3][i] = pack2(h6, h7);
        }
#pragma unroll
        for (int i = 0; i < 4; i++) {
            *(ulonglong2*)(ab + stofs[2*i+0]) = make_ulonglong2(hp[0][i], hp[1][i]);
            *(ulonglong2*)(ab + stofs[2*i+1]) = make_ulonglong2(hp[2][i], hp[3][i]);
        }
        __syncwarp();
    } else {
        // d_a4 = w5 (.) silu'(a4), stored sample-major; sp4 never materialized.
        float w5a[4] = {w5v.x, w5v.y, w5v.z, w5v.w};
#pragma unroll
        for (int p = 0; p < 3; p++) {
            float d0[4], d1[4];
#pragma unroll
            for (int i = 0; i < 4; i++) {
                float a0, a1; unpack2(acc[p][i], a0, a1);
                d0[i] = w5a[i] * silu_prime(a0);
                d1[i] = w5a[i] * silu_prime(a1);
            }
            st4(dbuf + (2*p    ) * HDIM + 4 * t, make_float4(d0[0], d0[1], d0[2], d0[3]));
            st4(dbuf + (2*p + 1) * HDIM + 4 * t, make_float4(d1[0], d1[1], d1[2], d1[3]));
        }
        {
            float d6[4], d7[4];
#pragma unroll
            for (int i = 0; i < 4; i++) {
                d6[i] = w5a[i] * silu_prime(sacc[0][i]);
                d7[i] = w5a[i] * silu_prime(sacc[1][i]);
            }
            st4(dbuf + 6 * HDIM + 4 * t, make_float4(d6[0], d6[1], d6[2], d6[3]));
            st4(dbuf + 7 * HDIM + 4 * t, make_float4(d7[0], d7[1], d7[2], d7[3]));
        }
        __syncwarp();
    }
}

// Backward through W^T, 8 samples. accf[s][i] = sum_j d[s][j] * W[4t+i][j].
// Samples 0-5: j-packed FFMA2 (even/odd j in the f32x2 lanes, hsum at end).
// Samples 6-7: scalar FFMA, sequential j within each quad (minor
// reassociation vs packed; error at the 1e-7 level).
static __device__ __forceinline__ void bwd8(const char* __restrict__ Ws,
                                            const char* __restrict__ db,
                                            int t, int t7, float accf[8][4])
{
    ull acc[6][4];
    float sacc[2][4];
    const ull z = pack2(0.0f, 0.0f);
#pragma unroll
    for (int s = 0; s < 6; s++)
#pragma unroll
        for (int i = 0; i < 4; i++) acc[s][i] = z;
#pragma unroll
    for (int si = 0; si < 2; si++)
#pragma unroll
        for (int i = 0; i < 4; i++) sacc[si][i] = 0.0f;

    const char* wr0 = Ws + (4 * t + 0) * 512;
    const char* wr1 = Ws + (4 * t + 1) * 512;
    const char* wr2 = Ws + (4 * t + 2) * 512;
    const char* wr3 = Ws + (4 * t + 3) * 512;

#pragma unroll 1
    for (int qi = 0; qi < 8; qi++) {          // q = 8g + qi covers all 32 quads
        const int wo   = (qi ^ t7) << 4;
        const int dofs = qi << 4;
#pragma unroll
        for (int g = 0; g < 4; g++) {
            const int go = g * 128;
            ulonglong2 w0 = *(const ulonglong2*)(wr0 + go + wo);
            ulonglong2 w1 = *(const ulonglong2*)(wr1 + go + wo);
            ulonglong2 w2 = *(const ulonglong2*)(wr2 + go + wo);
            ulonglong2 w3 = *(const ulonglong2*)(wr3 + go + wo);
            // scalar views of the same registers (mov.b64 splits, reg-aliased)
            float w0a, w0b, w0c, w0d; unpack2(w0.x, w0a, w0b); unpack2(w0.y, w0c, w0d);
            float w1a, w1b, w1c, w1d; unpack2(w1.x, w1a, w1b); unpack2(w1.y, w1c, w1d);
            float w2a, w2b, w2c, w2d; unpack2(w2.x, w2a, w2b); unpack2(w2.y, w2c, w2d);
            float w3a, w3b, w3c, w3d; unpack2(w3.x, w3a, w3b); unpack2(w3.y, w3c, w3d);
#pragma unroll
            for (int s = 0; s < 6; s++) {
                ulonglong2 dv = *(const ulonglong2*)(db + s * 512 + go + dofs);
                fma2(acc[s][0], dv.x, w0.x);
                fma2(acc[s][1], dv.x, w1.x);
                fma2(acc[s][2], dv.x, w2.x);
                fma2(acc[s][3], dv.x, w3.x);
                fma2(acc[s][0], dv.y, w0.y);
                fma2(acc[s][1], dv.y, w1.y);
                fma2(acc[s][2], dv.y, w2.y);
                fma2(acc[s][3], dv.y, w3.y);
            }
#pragma unroll
            for (int si = 0; si < 2; si++) {
                float4 dv = *(const float4*)(db + (6 + si) * 512 + go + dofs);
                sacc[si][0] = fmaf(dv.x, w0a, sacc[si][0]);
                sacc[si][1] = fmaf(dv.x, w1a, sacc[si][1]);
                sacc[si][2] = fmaf(dv.x, w2a, sacc[si][2]);
                sacc[si][3] = fmaf(dv.x, w3a, sacc[si][3]);
                sacc[si][0] = fmaf(dv.y, w0b, sacc[si][0]);
                sacc[si][1] = fmaf(dv.y, w1b, sacc[si][1]);
                sacc[si][2] = fmaf(dv.y, w2b, sacc[si][2]);
                sacc[si][3] = fmaf(dv.y, w3b, sacc[si][3]);
                sacc[si][0] = fmaf(dv.z, w0c, sacc[si][0]);
                sacc[si][1] = fmaf(dv.z, w1c, sacc[si][1]);
                sacc[si][2] = fmaf(dv.z, w2c, sacc[si][2]);
                sacc[si][3] = fmaf(dv.z, w3c, sacc[si][3]);
                sacc[si][0] = fmaf(dv.w, w0d, sacc[si][0]);
                sacc[si][1] = fmaf(dv.w, w1d, sacc[si][1]);
                sacc[si][2] = fmaf(dv.w, w2d, sacc[si][2]);
                sacc[si][3] = fmaf(dv.w, w3d, sacc[si][3]);
            }
        }
    }
    __syncwarp();   // everyone done reading db

#pragma unroll
    for (int s = 0; s < 6; s++)
#pragma unroll
        for (int i = 0; i < 4; i++) {
            float lo, hi; unpack2(acc[s][i], lo, hi);
            accf[s][i] = lo + hi;
        }
#pragma unroll
    for (int si = 0; si < 2; si++)
#pragma unroll
        for (int i = 0; i < 4; i++)
            accf[6 + si][i] = sacc[si][i];
}

// smem: 3 x 64KB swizzled weights + 8 warps x 4KB buffers = 229376 B
extern "C" __global__ void __launch_bounds__(256, 1)
ebm_langevin_kernel(const float* __restrict__ x0,
                    const float* __restrict__ w1, const float* __restrict__ b1,
                    const float* __restrict__ w2, const float* __restrict__ b2,
                    const float* __restrict__ w3, const float* __restrict__ b3,
                    const float* __restrict__ w4, const float* __restrict__ b4,
                    const float* __restrict__ w5, const float* __restrict__ b5,
                    const float* __restrict__ noise,
                    float* __restrict__ out)
{
    extern __shared__ float smem[];
    float* w2s = smem;
    float* w3s = smem + 16384;
    float* w4s = smem + 32768;
    char*  bufs = (char*)(smem + 49152);

    const int tid = threadIdx.x;

    // Cooperative swizzled weight load: quad q of row k -> slot q ^ ((k>>2)&7).
    for (int idx = tid; idx < 3 * 4096; idx += 256) {
        int m   = idx >> 12;
        int rem = idx & 4095;
        int k   = rem >> 5;
        int q   = rem & 31;
        const float* src = (m == 0) ? w2 : (m == 1) ? w3 : w4;
        float*       dst = (m == 0) ? w2s : (m == 1) ? w3s : w4s;
        reinterpret_cast<float4*>(dst)[k * 32 + (q ^ ((k >> 2) & 7))] =
            reinterpret_cast<const float4*>(src)[rem];
    }
    __syncthreads();

    const int warp = tid >> 5;
    const int t    = tid & 31;
    const int t7   = t & 7;
    char*  ab   = bufs + warp * 4096;
    float* dbuf = (float*)ab;

    const char* w2c = (const char*)w2s;
    const char* w3c = (const char*)w3s;
    const char* w4c = (const char*)w4s;

    // Per-lane activation-store offsets (conflict-free swizzled ST.128):
    // k = 4t+i, half -> byte ((8t + 2i + half) ^ (t&7)) * 16
    int stofs[8];
#pragma unroll
    for (int i = 0; i < 4; i++)
#pragma unroll
        for (int half = 0; half < 2; half++)
            stofs[2 * i + half] = (t << 7) + ((((i << 1) | half) ^ t7) << 4);

    const int gw = blockIdx.x * 8 + warp;
    const int nw = gridDim.x * 8;

    const float4 w1r0 = ld4(w1 + 4 * t);
    const float4 w1r1 = ld4(w1 + HDIM + 4 * t);
    const float4 b1v  = ld4(b1 + 4 * t);
    const float4 b2v  = ld4(b2 + 4 * t);
    const float4 b3v  = ld4(b3 + 4 * t);
    const float4 b4v  = ld4(b4 + 4 * t);
    const float4 w5v  = ld4(w5 + 4 * t);
    (void)b5;
    float w1A[4] = {w1r0.x, w1r0.y, w1r0.z, w1r0.w};
    float w1B[4] = {w1r1.x, w1r1.y, w1r1.z, w1r1.w};
    float bb1[4] = {b1v.x,  b1v.y,  b1v.z,  b1v.w};

    for (int b = gw; b < NCH / 8; b += nw) {
        const int base = b * 8;
        float xs[8][2];
#pragma unroll
        for (int s = 0; s < 8; s++) {
            xs[s][0] = x0[(base + s) * 2 + 0];
            xs[s][1] = x0[(base + s) * 2 + 1];
        }

        // fp32 silu' caches: sp[i*8 + s], i = output quad-lane, s = sample.
        float sp1[32], sp2[32], sp3[32];

        for (int step = 0; step < NSTEPS; step++) {
            // ---- forward L1: 2 -> 128 (writes pair-major activation buf) ----
            {
                ull hp[4][4];
#pragma unroll
                for (int p = 0; p < 4; p++)
#pragma unroll
                    for (int i = 0; i < 4; i++) {
                        float a0 = fmaf(xs[2*p  ][0], w1A[i],
                                   fmaf(xs[2*p  ][1], w1B[i], bb1[i]));
                        float a1 = fmaf(xs[2*p+1][0], w1A[i],
                                   fmaf(xs[2*p+1][1], w1B[i], bb1[i]));
                        float h0, s0, h1, s1;
                        silu_act(a0, h0, s0);
                        silu_act(a1, h1, s1);
                        sp1[i * 8 + 2 * p]     = s0;
                        sp1[i * 8 + 2 * p + 1] = s1;
                        hp[p][i] = pack2(h0, h1);
                    }
#pragma unroll
                for (int i = 0; i < 4; i++) {
                    *(ulonglong2*)(ab + stofs[2*i+0]) = make_ulonglong2(hp[0][i], hp[1][i]);
                    *(ulonglong2*)(ab + stofs[2*i+1]) = make_ulonglong2(hp[2][i], hp[3][i]);
                }
                __syncwarp();
            }

            fwd8<false>(w2c, ab, b2v, sp2, t, stofs, w5v, dbuf);  // h1 -> h2
            fwd8<false>(w3c, ab, b3v, sp3, t, stofs, w5v, dbuf);  // h2 -> h3
            fwd8<true >(w4c, ab, b4v, sp3 /*unused*/, t, stofs, w5v, dbuf); // seed d_a4

            float accf[8][4];
            // d_a3 = (d_a4 @ W4^T) * silu'(a3)
            bwd8(w4c, (const char*)dbuf, t, t7, accf);
#pragma unroll
            for (int s = 0; s < 8; s++) {
                st4(dbuf + s * HDIM + 4 * t,
                    make_float4(accf[s][0] * sp3[0 * 8 + s],
                                accf[s][1] * sp3[1 * 8 + s],
                                accf[s][2] * sp3[2 * 8 + s],
                                accf[s][3] * sp3[3 * 8 + s]));
            }
            __syncwarp();
            // d_a2 = (d_a3 @ W3^T) * silu'(a2)
            bwd8(w3c, (const char*)dbuf, t, t7, accf);
#pragma unroll
            for (int s = 0; s < 8; s++) {
                st4(dbuf + s * HDIM + 4 * t,
                    make_float4(accf[s][0] * sp2[0 * 8 + s],
                                accf[s][1] * sp2[1 * 8 + s],
                                accf[s][2] * sp2[2 * 8 + s],
                                accf[s][3] * sp2[3 * 8 + s]));
            }
            __syncwarp();
            // d_a1 = (d_a2 @ W2^T) * silu'(a1) ; dx = d_a1 @ W1^T
            bwd8(w2c, (const char*)dbuf, t, t7, accf);

            float pdx[8][2];
#pragma unroll
            for (int s = 0; s < 8; s++) {
                float d0 = accf[s][0] * sp1[0 * 8 + s];
                float d1 = accf[s][1] * sp1[1 * 8 + s];
                float d2 = accf[s][2] * sp1[2 * 8 + s];
                float d3 = accf[s][3] * sp1[3 * 8 + s];
                pdx[s][0] = fmaf(d0, w1A[0], fmaf(d1, w1A[1],
                            fmaf(d2, w1A[2], d3 * w1A[3])));
                pdx[s][1] = fmaf(d0, w1B[0], fmaf(d1, w1B[1],
                            fmaf(d2, w1B[2], d3 * w1B[3])));
            }
            // butterfly reduce -> every lane holds full dx for all 8 samples
#pragma unroll
            for (int off = 16; off > 0; off >>= 1) {
#pragma unroll
                for (int s = 0; s < 8; s++) {
                    pdx[s][0] += __shfl_xor_sync(0xffffffffu, pdx[s][0], off);
                    pdx[s][1] += __shfl_xor_sync(0xffffffffu, pdx[s][1], off);
                }
            }

            // ---- Langevin update (replicated identically in all lanes) ----
            float fi  = (float)step;
            float eps = 10.0f * (1.0f - fi / 60.0f);
            float sq  = sqrtf(2.0f * eps);
            const float4* nzp = (const float4*)(noise + ((size_t)step * NCH + base) * 2);
            float4 n0 = nzp[0], n1 = nzp[1], n2 = nzp[2], n3 = nzp[3];
            float nzv[16] = {n0.x, n0.y, n0.z, n0.w, n1.x, n1.y, n1.z, n1.w,
                             n2.x, n2.y, n2.z, n2.w, n3.x, n3.y, n3.z, n3.w};
#pragma unroll
            for (int s = 0; s < 8; s++) {
#pragma unroll
                for (int c = 0; c < 2; c++) {
                    float nz = nzv[2 * s + c];
                    float g  = fminf(fmaxf(pdx[s][c], -0.03f), 0.03f);
                    float xv = xs[s][c] + sq * nz * 0.005f + eps * g;
                    xs[s][c] = fminf(fmaxf(xv, -2.43f), 3.05f);
                }
            }
            // next L1 store is safe: bwd8 already syncwarp'd after its reads
        }

        if (t < 16) {
            out[base * 2 + t] = xs[t >> 1][t & 1];
        }
    }
}

extern "C" void kernel_launch(void* const* d_in, const int* in_sizes, int n_in,
                              void* d_out, int out_size)
{
    const float* x0    = (const float*)d_in[0];
    const float* w1    = (const float*)d_in[1];
    const float* b1    = (const float*)d_in[2];
    const float* w2    = (const float*)d_in[3];
    const float* b2    = (const float*)d_in[4];
    const float* w3    = (const float*)d_in[5];
    const float* b3    = (const float*)d_in[6];
    const float* w4    = (const float*)d_in[7];
    const float* b4    = (const float*)d_in[8];
    const float* w5    = (const float*)d_in[9];
    const float* b5    = (const float*)d_in[10];
    const float* noise = (const float*)d_in[11];

    const int smemBytes = 57344 * (int)sizeof(float);   // 229376
    cudaFuncSetAttribute(ebm_langevin_kernel,
                         cudaFuncAttributeMaxDynamicSharedMemorySize, smemBytes);

    int nsm = 148;
    cudaDeviceGetAttribute(&nsm, cudaDevAttrMultiProcessorCount, 0);

    ebm_langevin_kernel<<<nsm, 256, smemBytes>>>(
        x0, w1, b1, w2, b2, w3, b3, w4, b4, w5, b5, noise, (float*)d_out);
}

// round 15
// speedup vs baseline: 1.1492x; 1.0010x over previous
#include <cuda_runtime.h>
#include <math.h>

#define NCH    131072
#define NSTEPS 60
#define HDIM   128

typedef unsigned long long ull;

// ---------------------------------------------------------------------------
// Packed fp32x2 helpers (sm_103a FFMA2 — only reachable via PTX f32x2 ops).
// FFMA2 reads 3x64-bit operands -> 3 even + 3 odd bank registers -> rt 3
// (RF-banking law). Scalar FFMA is rt 2. The fma PIPE accepts 1 op / 2 cyc,
// so a mixed F2+F stream reaches ~0.8 MACs/cyc vs 0.67 for pure FFMA2.
// Samples 0-5 stay FFMA2-packed; samples 6-7 run scalar FFMA.
// ---------------------------------------------------------------------------
static __device__ __forceinline__ ull pack2(float lo, float hi) {
    ull r; asm("mov.b64 %0, {%1, %2};" : "=l"(r) : "f"(lo), "f"(hi)); return r;
}
static __device__ __forceinline__ void unpack2(ull v, float& lo, float& hi) {
    asm("mov.b64 {%0, %1}, %2;" : "=f"(lo), "=f"(hi) : "l"(v));
}
static __device__ __forceinline__ void fma2(ull& c, ull a, ull b) {
    asm("fma.rn.f32x2 %0, %1, %2, %0;" : "+l"(c) : "l"(a), "l"(b));
}

static __device__ __forceinline__ float4 ld4(const float* p) {
    return *reinterpret_cast<const float4*>(p);
}
static __device__ __forceinline__ void st4(float* p, float4 v) {
    *reinterpret_cast<float4*>(p) = v;
}

static __device__ __forceinline__ void silu_act(float a, float& h, float& sp) {
    float e   = __expf(-a);
    float sig = __fdividef(1.0f, 1.0f + e);
    h  = a * sig;
    sp = sig * (1.0f + a * (1.0f - sig));
}
static __device__ __forceinline__ float silu_prime(float a) {
    float e   = __expf(-a);
    float sig = __fdividef(1.0f, 1.0f + e);
    return sig * (1.0f + a * (1.0f - sig));
}

// ---------------------------------------------------------------------------
// Layouts identical to R8/R13 (validated):
// Activations pair-major swizzled 16B slots: slot(k,half)=(2k+half)^((k>>2)&7);
// half0 = f32x2 pairs (s0,s1),(s2,s3); half1 = (s4,s5),(s6,s7).
// Backward d-buffer sample-major: d[s][j] at s*512 + 4j.
// Weights: quad q of row k at slot q ^ ((k>>2)&7), row stride 512 B.
// ---------------------------------------------------------------------------

// Forward 128->128, 8 samples. Samples 0-5: sample-pair FFMA2 (weights packed
// (w,w) via mov.b64). Samples 6-7: scalar FFMA on the same loaded registers.
// SEED=true (layer 4): skip h store; write d_a4 = w5 (.) silu'(a4) into dbuf.
template<bool SEED>
static __device__ __forceinline__ void fwd8(const char* __restrict__ Ws,
                                            char* __restrict__ ab,
                                            float4 bv, float* __restrict__ sp,
                                            int t, const int* stofs,
                                            float4 w5v, float* __restrict__ dbuf)
{
    ull  acc[3][4];      // sample-pairs (s0,s1),(s2,s3),(s4,s5) x outputs
    float sacc[2][4];    // samples s6, s7 (scalar) x outputs
    {
        ull bd0 = pack2(bv.x, bv.x), bd1 = pack2(bv.y, bv.y);
        ull bd2 = pack2(bv.z, bv.z), bd3 = pack2(bv.w, bv.w);
#pragma unroll
        for (int p = 0; p < 3; p++) {
            acc[p][0] = bd0; acc[p][1] = bd1; acc[p][2] = bd2; acc[p][3] = bd3;
        }
#pragma unroll
        for (int si = 0; si < 2; si++) {
            sacc[si][0] = bv.x; sacc[si][1] = bv.y;
            sacc[si][2] = bv.z; sacc[si][3] = bv.w;
        }
    }
    const int t16 = t << 4;
#pragma unroll 1
    for (int k0 = 0; k0 < HDIM; k0 += 32) {   // swizzle period
        const char* wb = Ws + k0 * 512;
        const char* hb = ab + k0 * 32;
#pragma unroll
        for (int kk = 0; kk < 32; kk++) {
            const int c = (kk >> 2) & 7;      // compile-time
            float4 w = *(const float4*)(wb + kk * 512 + (t16 ^ (c << 4)));
            ull wd0 = pack2(w.x, w.x), wd1 = pack2(w.y, w.y);
            ull wd2 = pack2(w.z, w.z), wd3 = pack2(w.w, w.w);
            ulonglong2 hA = *(const ulonglong2*)(hb + (((2*kk    ) ^ c) << 4));
            float4     hB = *(const float4*)   (hb + (((2*kk + 1) ^ c) << 4));
            ull hp45 = pack2(hB.x, hB.y);     // (s4,s5) pair (reg-aliased)
            // packed pairs (12 F2) interleaved with scalar s6,s7 (8 F)
            fma2(acc[0][0], hA.x, wd0); fma2(acc[0][1], hA.x, wd1);
            sacc[0][0] = fmaf(hB.z, w.x, sacc[0][0]);
            sacc[1][0] = fmaf(hB.w, w.x, sacc[1][0]);
            fma2(acc[0][2], hA.x, wd2); fma2(acc[0][3], hA.x, wd3);
            sacc[0][1] = fmaf(hB.z, w.y, sacc[0][1]);
            sacc[1][1] = fmaf(hB.w, w.y, sacc[1][1]);
            fma2(acc[1][0], hA.y, wd0); fma2(acc[1][1], hA.y, wd1);
            sacc[0][2] = fmaf(hB.z, w.z, sacc[0][2]);
            sacc[1][2] = fmaf(hB.w, w.z, sacc[1][2]);
            fma2(acc[1][2], hA.y, wd2); fma2(acc[1][3], hA.y, wd3);
            sacc[0][3] = fmaf(hB.z, w.w, sacc[0][3]);
            sacc[1][3] = fmaf(hB.w, w.w, sacc[1][3]);
            fma2(acc[2][0], hp45, wd0); fma2(acc[2][1], hp45, wd1);
            fma2(acc[2][2], hp45, wd2); fma2(acc[2][3], hp45, wd3);
        }
    }
    __syncwarp();   // everyone done reading ab (may be overwritten below)

    if (!SEED) {
        ull hp[4][4];
#pragma unroll
        for (int p = 0; p < 3; p++)
#pragma unroll
            for (int i = 0; i < 4; i++) {
                float a0, a1; unpack2(acc[p][i], a0, a1);
                float h0, s0, h1, s1;
                silu_act(a0, h0, s0);
                silu_act(a1, h1, s1);
                sp[i * 8 + 2 * p]     = s0;
                sp[i * 8 + 2 * p + 1] = s1;
                hp[p][i] = pack2(h0, h1);
            }
#pragma unroll
        for (int i = 0; i < 4; i++) {
            float h6, s6, h7, s7;
            silu_act(sacc[0][i], h6, s6);
            silu_act(sacc[1][i], h7, s7);
            sp[i * 8 + 6] = s6;
            sp[i * 8 + 7] = s7;
            hp[3][i] = pack2(h6, h7);
        }
#pragma unroll
        for (int i = 0; i < 4; i++) {
            *(ulonglong2*)(ab + stofs[2*i+0]) = make_ulonglong2(hp[0][i], hp[1][i]);
            *(ulonglong2*)(ab + stofs[2*i+1]) = make_ulonglong2(hp[2][i], hp[3][i]);
        }
        __syncwarp();
    } else {
        // d_a4 = w5 (.) silu'(a4), stored sample-major; sp4 never materialized.
        float w5a[4] = {w5v.x, w5v.y, w5v.z, w5v.w};
#pragma unroll
        for (int p = 0; p < 3; p++) {
            float d0[4], d1[4];
#pragma unroll
            for (int i = 0; i < 4; i++) {
                float a0, a1; unpack2(acc[p][i], a0, a1);
                d0[i] = w5a[i] * silu_prime(a0);
                d1[i] = w5a[i] * silu_prime(a1);
            }
            st4(dbuf + (2*p    ) * HDIM + 4 * t, make_float4(d0[0], d0[1], d0[2], d0[3]));
            st4(dbuf + (2*p + 1) * HDIM + 4 * t, make_float4(d1[0], d1[1], d1[2], d1[3]));
        }
        {
            float d6[4], d7[4];
#pragma unroll
            for (int i = 0; i < 4; i++) {
                d6[i] = w5a[i] * silu_prime(sacc[0][i]);
                d7[i] = w5a[i] * silu_prime(sacc[1][i]);
            }
            st4(dbuf + 6 * HDIM + 4 * t, make_float4(d6[0], d6[1], d6[2], d6[3]));
            st4(dbuf + 7 * HDIM + 4 * t, make_float4(d7[0], d7[1], d7[2], d7[3]));
        }
        __syncwarp();
    }
}

// Backward through W^T, 8 samples. accf[s][i] = sum_j d[s][j] * W[4t+i][j].
// Samples 0-5: j-packed FFMA2 (even/odd j in the f32x2 lanes, hsum at end).
// Samples 6-7: scalar FFMA, sequential j within each quad (minor
// reassociation vs packed; error at the 1e-7 level).
static __device__ __forceinline__ void bwd8(const char* __restrict__ Ws,
                                            const char* __restrict__ db,
                                            int t, int t7, float accf[8][4])
{
    ull acc[6][4];
    float sacc[2][4];
    const ull z = pack2(0.0f, 0.0f);
#pragma unroll
    for (int s = 0; s < 6; s++)
#pragma unroll
        for (int i = 0; i < 4; i++) acc[s][i] = z;
#pragma unroll
    for (int si = 0; si < 2; si++)
#pragma unroll
        for (int i = 0; i < 4; i++) sacc[si][i] = 0.0f;

    const char* wr0 = Ws + (4 * t + 0) * 512;
    const char* wr1 = Ws + (4 * t + 1) * 512;
    const char* wr2 = Ws + (4 * t + 2) * 512;
    const char* wr3 = Ws + (4 * t + 3) * 512;

#pragma unroll 1
    for (int qi = 0; qi < 8; qi++) {          // q = 8g + qi covers all 32 quads
        const int wo   = (qi ^ t7) << 4;
        const int dofs = qi << 4;
#pragma unroll
        for (int g = 0; g < 4; g++) {
            const int go = g * 128;
            ulonglong2 w0 = *(const ulonglong2*)(wr0 + go + wo);
            ulonglong2 w1 = *(const ulonglong2*)(wr1 + go + wo);
            ulonglong2 w2 = *(const ulonglong2*)(wr2 + go + wo);
            ulonglong2 w3 = *(const ulonglong2*)(wr3 + go + wo);
            // scalar views of the same registers (mov.b64 splits, reg-aliased)
            float w0a, w0b, w0c, w0d; unpack2(w0.x, w0a, w0b); unpack2(w0.y, w0c, w0d);
            float w1a, w1b, w1c, w1d; unpack2(w1.x, w1a, w1b); unpack2(w1.y, w1c, w1d);
            float w2a, w2b, w2c, w2d; unpack2(w2.x, w2a, w2b); unpack2(w2.y, w2c, w2d);
            float w3a, w3b, w3c, w3d; unpack2(w3.x, w3a, w3b); unpack2(w3.y, w3c, w3d);
#pragma unroll
            for (int s = 0; s < 6; s++) {
                ulonglong2 dv = *(const ulonglong2*)(db + s * 512 + go + dofs);
                fma2(acc[s][0], dv.x, w0.x);
                fma2(acc[s][1], dv.x, w1.x);
                fma2(acc[s][2], dv.x, w2.x);
                fma2(acc[s][3], dv.x, w3.x);
                fma2(acc[s][0], dv.y, w0.y);
                fma2(acc[s][1], dv.y, w1.y);
                fma2(acc[s][2], dv.y, w2.y);
                fma2(acc[s][3], dv.y, w3.y);
            }
#pragma unroll
            for (int si = 0; si < 2; si++) {
                float4 dv = *(const float4*)(db + (6 + si) * 512 + go + dofs);
                sacc[si][0] = fmaf(dv.x, w0a, sacc[si][0]);
                sacc[si][1] = fmaf(dv.x, w1a, sacc[si][1]);
                sacc[si][2] = fmaf(dv.x, w2a, sacc[si][2]);
                sacc[si][3] = fmaf(dv.x, w3a, sacc[si][3]);
                sacc[si][0] = fmaf(dv.y, w0b, sacc[si][0]);
                sacc[si][1] = fmaf(dv.y, w1b, sacc[si][1]);
                sacc[si][2] = fmaf(dv.y, w2b, sacc[si][2]);
                sacc[si][3] = fmaf(dv.y, w3b, sacc[si][3]);
                sacc[si][0] = fmaf(dv.z, w0c, sacc[si][0]);
                sacc[si][1] = fmaf(dv.z, w1c, sacc[si][1]);
                sacc[si][2] = fmaf(dv.z, w2c, sacc[si][2]);
                sacc[si][3] = fmaf(dv.z, w3c, sacc[si][3]);
                sacc[si][0] = fmaf(dv.w, w0d, sacc[si][0]);
                sacc[si][1] = fmaf(dv.w, w1d, sacc[si][1]);
                sacc[si][2] = fmaf(dv.w, w2d, sacc[si][2]);
                sacc[si][3] = fmaf(dv.w, w3d, sacc[si][3]);
            }
        }
    }
    __syncwarp();   // everyone done reading db

#pragma unroll
    for (int s = 0; s < 6; s++)
#pragma unroll
        for (int i = 0; i < 4; i++) {
            float lo, hi; unpack2(acc[s][i], lo, hi);
            accf[s][i] = lo + hi;
        }
#pragma unroll
    for (int si = 0; si < 2; si++)
#pragma unroll
        for (int i = 0; i < 4; i++)
            accf[6 + si][i] = sacc[si][i];
}

// smem: 3 x 64KB swizzled weights + 8 warps x 4KB buffers = 229376 B
extern "C" __global__ void __launch_bounds__(256, 1)
ebm_langevin_kernel(const float* __restrict__ x0,
                    const float* __restrict__ w1, const float* __restrict__ b1,
                    const float* __restrict__ w2, const float* __restrict__ b2,
                    const float* __restrict__ w3, const float* __restrict__ b3,
                    const float* __restrict__ w4, const float* __restrict__ b4,
                    const float* __restrict__ w5, const float* __restrict__ b5,
                    const float* __restrict__ noise,
                    float* __restrict__ out)
{
    extern __shared__ float smem[];
    float* w2s = smem;
    float* w3s = smem + 16384;
    float* w4s = smem + 32768;
    char*  bufs = (char*)(smem + 49152);

    const int tid = threadIdx.x;

    // Cooperative swizzled weight load: quad q of row k -> slot q ^ ((k>>2)&7).
    for (int idx = tid; idx < 3 * 4096; idx += 256) {
        int m   = idx >> 12;
        int rem = idx & 4095;
        int k   = rem >> 5;
        int q   = rem & 31;
        const float* src = (m == 0) ? w2 : (m == 1) ? w3 : w4;
        float*       dst = (m == 0) ? w2s : (m == 1) ? w3s : w4s;
        reinterpret_cast<float4*>(dst)[k * 32 + (q ^ ((k >> 2) & 7))] =
            reinterpret_cast<const float4*>(src)[rem];
    }
    __syncthreads();

    const int warp = tid >> 5;
    const int t    = tid & 31;
    const int t7   = t & 7;
    char*  ab   = bufs + warp * 4096;
    float* dbuf = (float*)ab;

    const char* w2c = (const char*)w2s;
    const char* w3c = (const char*)w3s;
    const char* w4c = (const char*)w4s;

    // Per-lane activation-store offsets (conflict-free swizzled ST.128):
    // k = 4t+i, half -> byte ((8t + 2i + half) ^ (t&7)) * 16
    int stofs[8];
#pragma unroll
    for (int i = 0; i < 4; i++)
#pragma unroll
        for (int half = 0; half < 2; half++)
            stofs[2 * i + half] = (t << 7) + ((((i << 1) | half) ^ t7) << 4);

    const int gw = blockIdx.x * 8 + warp;
    const int nw = gridDim.x * 8;

    const float4 w1r0 = ld4(w1 + 4 * t);
    const float4 w1r1 = ld4(w1 + HDIM + 4 * t);
    const float4 b1v  = ld4(b1 + 4 * t);
    const float4 b2v  = ld4(b2 + 4 * t);
    const float4 b3v  = ld4(b3 + 4 * t);
    const float4 b4v  = ld4(b4 + 4 * t);
    const float4 w5v  = ld4(w5 + 4 * t);
    (void)b5;
    float w1A[4] = {w1r0.x, w1r0.y, w1r0.z, w1r0.w};
    float w1B[4] = {w1r1.x, w1r1.y, w1r1.z, w1r1.w};
    float bb1[4] = {b1v.x,  b1v.y,  b1v.z,  b1v.w};

    for (int b = gw; b < NCH / 8; b += nw) {
        const int base = b * 8;
        float xs[8][2];
#pragma unroll
        for (int s = 0; s < 8; s++) {
            xs[s][0] = x0[(base + s) * 2 + 0];
            xs[s][1] = x0[(base + s) * 2 + 1];
        }

        // fp32 silu' caches: sp[i*8 + s], i = output quad-lane, s = sample.
        float sp1[32], sp2[32], sp3[32];

        for (int step = 0; step < NSTEPS; step++) {
            // ---- forward L1: 2 -> 128 (writes pair-major activation buf) ----
            {
                ull hp[4][4];
#pragma unroll
                for (int p = 0; p < 4; p++)
#pragma unroll
                    for (int i = 0; i < 4; i++) {
                        float a0 = fmaf(xs[2*p  ][0], w1A[i],
                                   fmaf(xs[2*p  ][1], w1B[i], bb1[i]));
                        float a1 = fmaf(xs[2*p+1][0], w1A[i],
                                   fmaf(xs[2*p+1][1], w1B[i], bb1[i]));
                        float h0, s0, h1, s1;
                        silu_act(a0, h0, s0);
                        silu_act(a1, h1, s1);
                        sp1[i * 8 + 2 * p]     = s0;
                        sp1[i * 8 + 2 * p + 1] = s1;
                        hp[p][i] = pack2(h0, h1);
                    }
#pragma unroll
                for (int i = 0; i < 4; i++) {
                    *(ulonglong2*)(ab + stofs[2*i+0]) = make_ulonglong2(hp[0][i], hp[1][i]);
                    *(ulonglong2*)(ab + stofs[2*i+1]) = make_ulonglong2(hp[2][i], hp[3][i]);
                }
                __syncwarp();
            }

            fwd8<false>(w2c, ab, b2v, sp2, t, stofs, w5v, dbuf);  // h1 -> h2
            fwd8<false>(w3c, ab, b3v, sp3, t, stofs, w5v, dbuf);  // h2 -> h3
            fwd8<true >(w4c, ab, b4v, sp3 /*unused*/, t, stofs, w5v, dbuf); // seed d_a4

            float accf[8][4];
            // d_a3 = (d_a4 @ W4^T) * silu'(a3)
            bwd8(w4c, (const char*)dbuf, t, t7, accf);
#pragma unroll
            for (int s = 0; s < 8; s++) {
                st4(dbuf + s * HDIM + 4 * t,
                    make_float4(accf[s][0] * sp3[0 * 8 + s],
                                accf[s][1] * sp3[1 * 8 + s],
                                accf[s][2] * sp3[2 * 8 + s],
                                accf[s][3] * sp3[3 * 8 + s]));
            }
            __syncwarp();
            // d_a2 = (d_a3 @ W3^T) * silu'(a2)
            bwd8(w3c, (const char*)dbuf, t, t7, accf);
#pragma unroll
            for (int s = 0; s < 8; s++) {
                st4(dbuf + s * HDIM + 4 * t,
                    make_float4(accf[s][0] * sp2[0 * 8 + s],
                                accf[s][1] * sp2[1 * 8 + s],
                                accf[s][2] * sp2[2 * 8 + s],
                                accf[s][3] * sp2[3 * 8 + s]));
            }
            __syncwarp();
            // d_a1 = (d_a2 @ W2^T) * silu'(a1) ; dx = d_a1 @ W1^T
            bwd8(w2c, (const char*)dbuf, t, t7, accf);

            float pdx[8][2];
#pragma unroll
            for (int s = 0; s < 8; s++) {
                float d0 = accf[s][0] * sp1[0 * 8 + s];
                float d1 = accf[s][1] * sp1[1 * 8 + s];
                float d2 = accf[s][2] * sp1[2 * 8 + s];
                float d3 = accf[s][3] * sp1[3 * 8 + s];
                pdx[s][0] = fmaf(d0, w1A[0], fmaf(d1, w1A[1],
                            fmaf(d2, w1A[2], d3 * w1A[3])));
                pdx[s][1] = fmaf(d0, w1B[0], fmaf(d1, w1B[1],
                            fmaf(d2, w1B[2], d3 * w1B[3])));
            }
            // butterfly reduce -> every lane holds full dx for all 8 samples
#pragma unroll
            for (int off = 16; off > 0; off >>= 1) {
#pragma unroll
                for (int s = 0; s < 8; s++) {
                    pdx[s][0] += __shfl_xor_sync(0xffffffffu, pdx[s][0], off);
                    pdx[s][1] += __shfl_xor_sync(0xffffffffu, pdx[s][1], off);
                }
            }

            // ---- Langevin update (replicated identically in all lanes) ----
            float fi  = (float)step;
            float eps = 10.0f * (1.0f - fi / 60.0f);
            float sq  = sqrtf(2.0f * eps);
            const float4* nzp = (const float4*)(noise + ((size_t)step * NCH + base) * 2);
            float4 n0 = nzp[0], n1 = nzp[1], n2 = nzp[2], n3 = nzp[3];
            float nzv[16] = {n0.x, n0.y, n0.z, n0.w, n1.x, n1.y, n1.z, n1.w,
                             n2.x, n2.y, n2.z, n2.w, n3.x, n3.y, n3.z, n3.w};
#pragma unroll
            for (int s = 0; s < 8; s++) {
#pragma unroll
                for (int c = 0; c < 2; c++) {
                    float nz = nzv[2 * s + c];
                    float g  = fminf(fmaxf(pdx[s][c], -0.03f), 0.03f);
                    float xv = xs[s][c] + sq * nz * 0.005f + eps * g;
                    xs[s][c] = fminf(fmaxf(xv, -2.43f), 3.05f);
                }
            }
            // next L1 store is safe: bwd8 already syncwarp'd after its reads
        }

        if (t < 16) {
            out[base * 2 + t] = xs[t >> 1][t & 1];
        }
    }
}

extern "C" void kernel_launch(void* const* d_in, const int* in_sizes, int n_in,
                              void* d_out, int out_size)
{
    const float* x0    = (const float*)d_in[0];
    const float* w1    = (const float*)d_in[1];
    const float* b1    = (const float*)d_in[2];
    const float* w2    = (const float*)d_in[3];
    const float* b2    = (const float*)d_in[4];
    const float* w3    = (const float*)d_in[5];
    const float* b3    = (const float*)d_in[6];
    const float* w4    = (const float*)d_in[7];
    const float* b4    = (const float*)d_in[8];
    const float* w5    = (const float*)d_in[9];
    const float* b5    = (const float*)d_in[10];
    const float* noise = (const float*)d_in[11];

    const int smemBytes = 57344 * (int)sizeof(float);   // 229376
    cudaFuncSetAttribute(ebm_langevin_kernel,
                         cudaFuncAttributeMaxDynamicSharedMemorySize, smemBytes);

    int nsm = 148;
    cudaDeviceGetAttribute(&nsm, cudaDevAttrMultiProcessorCount, 0);

    ebm_langevin_kernel<<<nsm, 256, smemBytes>>>(
        x0, w1, b1, w2, b2, w3, b3, w4, b4, w5, b5, noise, (float*)d_out);
}